// round 13
// baseline (speedup 1.0000x reference)
#include <cuda_runtime.h>
#include <cuda_fp16.h>
#include <cstdint>

#define BB 4
#define QL 1024
#define DM 1024
#define NHEAD 16
#define DH 64
#define MTOT (BB * QL)  // 4096

// fp32 scratch
__device__ float g_ao[(size_t)MTOT * DM];
// fp16 split operands
__device__ __half g_wh[(size_t)MTOT * DM];
__device__ __half g_wl[(size_t)MTOT * DM];
__device__ __half g_avh[(size_t)MTOT * DM];
__device__ __half g_bh[(size_t)4 * DM * DM];
__device__ __half g_bl[(size_t)4 * DM * DM];
// attention operands
__device__ __half g_qbh[(size_t)MTOT * DM];
__device__ __half g_qbl[(size_t)MTOT * DM];
__device__ __half g_cbh[(size_t)BB * NHEAD * QL * DH];
__device__ __half g_cbl[(size_t)BB * NHEAD * QL * DH];
__device__ __half g_vbh[(size_t)BB * NHEAD * QL * DH];
__device__ float g_ts[(size_t)BB * NHEAD * QL];

// ===========================================================================
// PTX helpers (portable sm_80/90-class only)
// ===========================================================================
__device__ __forceinline__ uint32_t smem_to_u32(const void* p) {
    uint32_t a;
    asm("{ .reg .u64 t; cvta.to.shared.u64 t, %1; cvt.u32.u64 %0, t; }"
        : "=r"(a) : "l"(p));
    return a;
}
#define CP_ASYNC16(s, g) \
    asm volatile("cp.async.cg.shared.global [%0], [%1], 16;" :: "r"(s), "l"(g) : "memory")
#define CP_ASYNC_COMMIT() asm volatile("cp.async.commit_group;" ::: "memory")
#define CP_ASYNC_WAIT1() asm volatile("cp.async.wait_group 1;" ::: "memory")
#define CP_ASYNC_WAIT2() asm volatile("cp.async.wait_group 2;" ::: "memory")

#define LDSM4(r0, r1, r2, r3, addr)                                            \
    asm volatile("ldmatrix.sync.aligned.m8n8.x4.shared.b16 {%0,%1,%2,%3}, [%4];" \
                 : "=r"(r0), "=r"(r1), "=r"(r2), "=r"(r3) : "r"(addr))
#define LDSM4T(r0, r1, r2, r3, addr)                                           \
    asm volatile("ldmatrix.sync.aligned.m8n8.x4.trans.shared.b16 {%0,%1,%2,%3}, [%4];" \
                 : "=r"(r0), "=r"(r1), "=r"(r2), "=r"(r3) : "r"(addr))

#define MMA_F16(d, a, b)                                                       \
    asm volatile("mma.sync.aligned.m16n8k16.row.col.f32.f16.f16.f32 "          \
                 "{%0,%1,%2,%3}, {%4,%5,%6,%7}, {%8,%9}, {%0,%1,%2,%3};"       \
                 : "+f"((d)[0]), "+f"((d)[1]), "+f"((d)[2]), "+f"((d)[3])      \
                 : "r"((a)[0]), "r"((a)[1]), "r"((a)[2]), "r"((a)[3]),         \
                   "r"((b)[0]), "r"((b)[1]))

// 64B rows (32 fp16), 4x16B chunks
#define SW64(row, ch) ((row) * 64 + (((ch) ^ (((row) >> 1) & 3)) << 4))
// 128B rows (64 fp16), 8x16B chunks
#define SWOFF(row, ch) ((row) * 128 + (((ch) ^ ((row) & 7)) << 4))

// ===========================================================================
// prep_all: z<4 -> weight transpose+split; z>=4 -> activation split (fp16)
// ===========================================================================
__global__ __launch_bounds__(256) void prep_all(
    const float* __restrict__ w,
    const float* __restrict__ s0, const float* __restrict__ s1,
    const float* __restrict__ s2, const float* __restrict__ s3,
    __half* __restrict__ wh, __half* __restrict__ wl,
    __half* __restrict__ bh, __half* __restrict__ bl)
{
    const int z = blockIdx.z;
    if (z >= 4) {
        int i = (((z - 4) * 32 + blockIdx.y) * 32 + blockIdx.x) * 256 + threadIdx.x;
        float4 a = ((const float4*)w)[i];
        __half h0 = __float2half_rn(a.x), h1 = __float2half_rn(a.y);
        __half h2 = __float2half_rn(a.z), h3 = __float2half_rn(a.w);
        ((__half2*)wh)[i * 2 + 0] = __halves2half2(h0, h1);
        ((__half2*)wh)[i * 2 + 1] = __halves2half2(h2, h3);
        ((__half2*)wl)[i * 2 + 0] = __halves2half2(
            __float2half_rn(a.x - __half2float(h0)),
            __float2half_rn(a.y - __half2float(h1)));
        ((__half2*)wl)[i * 2 + 1] = __halves2half2(
            __float2half_rn(a.z - __half2float(h2)),
            __float2half_rn(a.w - __half2float(h3)));
        return;
    }
    __shared__ float t[32][33];
    const float* S = z == 0 ? s0 : z == 1 ? s1 : z == 2 ? s2 : s3;
    __half* H = bh + (size_t)z * DM * DM;
    __half* L = bl + (size_t)z * DM * DM;
    const int x = blockIdx.x * 32, y = blockIdx.y * 32;
    const int tx = threadIdx.x & 31, ty = threadIdx.x >> 5;
#pragma unroll
    for (int i = 0; i < 32; i += 8)
        t[ty + i][tx] = S[(size_t)(y + ty + i) * DM + x + tx];
    __syncthreads();
    const int c = (threadIdx.x & 15) * 2;
    const int rb = threadIdx.x >> 4;
#pragma unroll
    for (int i = 0; i < 32; i += 16) {
        const int r = rb + i;
        float a0 = t[c][r], a1 = t[c + 1][r];
        __half h0 = __float2half_rn(a0), h1 = __float2half_rn(a1);
        size_t idx = (size_t)(x + r) * DM + y + c;
        *(__half2*)(H + idx) = __halves2half2(h0, h1);
        *(__half2*)(L + idx) = __halves2half2(
            __float2half_rn(a0 - __half2float(h0)),
            __float2half_rn(a1 - __half2float(h1)));
    }
}

// ===========================================================================
// QKV GEMM: CTA 64x128, 128 threads, 3 CTAs/SM (R12 exact).
// mat 0 (Q), 1 (K->C + ts): fp16x3. mat 2 (V): fp16 single pass.
// ===========================================================================
#define GK 1024
#define NCH 32
#define STG3 24576
#define SMEM_G64 (3 * STG3)

__global__ __launch_bounds__(128, 3) void gemm_qkv(
    const __half* __restrict__ Ah, const __half* __restrict__ Al,
    const __half* __restrict__ Bh, const __half* __restrict__ Bl,
    const float* __restrict__ remb, const float* __restrict__ rwb,
    const float* __restrict__ rbias,
    __half* __restrict__ Qh, __half* __restrict__ Ql,
    __half* __restrict__ Cbh, __half* __restrict__ Cbl,
    __half* __restrict__ Vbh,
    float* __restrict__ tsg)
{
    extern __shared__ char smem[];
    const uint32_t sb = smem_to_u32(smem);
    const int tid = threadIdx.x;
    const int wid = tid >> 5, lane = tid & 31;
    const int wm = wid >> 1, wn = wid & 1;
    const int mat = blockIdx.x >> 3;
    const int c0 = (blockIdx.x & 7) * 128;
    const int r0 = blockIdx.y * 64;
    const bool third = (mat != 2);

    const char* AgH = (const char*)(Ah + (size_t)r0 * GK);
    const char* AgL = (const char*)(Al + (size_t)r0 * GK);
    const char* BgH = (const char*)(Bh + (size_t)mat * DM * DM + (size_t)c0 * GK);
    const char* BgL = (const char*)(Bl + (size_t)mat * DM * DM + (size_t)c0 * GK);

    auto load_stage = [&](int st, int ck) {
        const uint32_t s0 = sb + st * STG3;
        const size_t gofs = (size_t)ck * 64;
#pragma unroll
        for (int h = 0; h < 2; ++h) {
            int idx = h * 128 + tid;
            int row = idx >> 2, ch = idx & 3;
            uint32_t o = SW64(row, ch);
            size_t g = (size_t)row * 2048 + gofs + ch * 16;
            CP_ASYNC16(s0 + o, AgH + g);
            if (third) CP_ASYNC16(s0 + 4096 + o, AgL + g);
        }
#pragma unroll
        for (int h = 0; h < 4; ++h) {
            int idx = h * 128 + tid;
            int row = idx >> 2, ch = idx & 3;
            uint32_t o = SW64(row, ch);
            size_t g = (size_t)row * 2048 + gofs + ch * 16;
            CP_ASYNC16(s0 + 8192 + o, BgH + g);
            if (third) CP_ASYNC16(s0 + 16384 + o, BgL + g);
        }
    };

    load_stage(0, 0); CP_ASYNC_COMMIT();
    load_stage(1, 1); CP_ASYNC_COMMIT();

    float acc[2][8][4];
#pragma unroll
    for (int mt = 0; mt < 2; ++mt)
#pragma unroll
        for (int nt = 0; nt < 8; ++nt)
#pragma unroll
            for (int r = 0; r < 4; ++r) acc[mt][nt][r] = 0.f;

    const int sub = lane >> 3, l7 = lane & 7;

    for (int i = 0; i < NCH; ++i) {
        CP_ASYNC_WAIT1();
        __syncthreads();
        if (i + 2 < NCH) load_stage((i + 2) % 3, i + 2);
        CP_ASYNC_COMMIT();

        const uint32_t sA = sb + (i % 3) * STG3;
        const uint32_t sB = sA + 8192;

#pragma unroll
        for (int ks = 0; ks < 2; ++ks) {
            uint32_t ah[2][4], al[2][4], bh2[4][2][2], bl2[4][2][2];
#pragma unroll
            for (int mt = 0; mt < 2; ++mt) {
                int row = wm * 32 + mt * 16 + ((sub & 1) << 3) + l7;
                int ch = 2 * ks + (sub >> 1);
                uint32_t off = SW64(row, ch);
                LDSM4(ah[mt][0], ah[mt][1], ah[mt][2], ah[mt][3], sA + off);
                if (third)
                    LDSM4(al[mt][0], al[mt][1], al[mt][2], al[mt][3],
                          sA + 4096 + off);
            }
#pragma unroll
            for (int ntp = 0; ntp < 4; ++ntp) {
                int row = wn * 64 + ntp * 16 + ((sub >> 1) << 3) + l7;
                int ch = 2 * ks + (sub & 1);
                uint32_t off = SW64(row, ch);
                LDSM4(bh2[ntp][0][0], bh2[ntp][0][1], bh2[ntp][1][0],
                      bh2[ntp][1][1], sB + off);
                if (third)
                    LDSM4(bl2[ntp][0][0], bl2[ntp][0][1], bl2[ntp][1][0],
                          bl2[ntp][1][1], sB + 8192 + off);
            }
#pragma unroll
            for (int ntp = 0; ntp < 4; ++ntp)
#pragma unroll
                for (int h = 0; h < 2; ++h)
#pragma unroll
                    for (int mt = 0; mt < 2; ++mt)
                        MMA_F16(acc[mt][2 * ntp + h], ah[mt], bh2[ntp][h]);
            if (third) {
#pragma unroll
                for (int ntp = 0; ntp < 4; ++ntp)
#pragma unroll
                    for (int h = 0; h < 2; ++h)
#pragma unroll
                        for (int mt = 0; mt < 2; ++mt) {
                            MMA_F16(acc[mt][2 * ntp + h], ah[mt], bl2[ntp][h]);
                            MMA_F16(acc[mt][2 * ntp + h], al[mt], bh2[ntp][h]);
                        }
            }
        }
    }

    if (mat == 0) {
#pragma unroll
        for (int mt = 0; mt < 2; ++mt)
#pragma unroll
            for (int nt = 0; nt < 8; ++nt) {
                int row = r0 + wm * 32 + mt * 16 + (lane >> 2);
                int col = c0 + wn * 64 + nt * 8 + 2 * (lane & 3);
                size_t p0 = (size_t)row * DM + col;
                size_t p1 = (size_t)(row + 8) * DM + col;
                float v0 = acc[mt][nt][0], v1 = acc[mt][nt][1];
                float v2 = acc[mt][nt][2], v3 = acc[mt][nt][3];
                __half2 h01 = __floats2half2_rn(v0, v1);
                __half2 h23 = __floats2half2_rn(v2, v3);
                *(__half2*)(Qh + p0) = h01;
                *(__half2*)(Qh + p1) = h23;
                *(__half2*)(Ql + p0) = __floats2half2_rn(
                    v0 - __half2float(h01.x), v1 - __half2float(h01.y));
                *(__half2*)(Ql + p1) = __floats2half2_rn(
                    v2 - __half2float(h23.x), v3 - __half2float(h23.y));
            }
    } else {
        const int n = ((blockIdx.x & 7) << 1) + wn;
        float rwv[8][2];
        if (mat == 1) {
#pragma unroll
            for (int nt = 0; nt < 8; ++nt) {
                float2 t = *(const float2*)(rwb + n * DH + nt * 8 + 2 * (lane & 3));
                rwv[nt][0] = t.x; rwv[nt][1] = t.y;
            }
        }
#pragma unroll
        for (int mt = 0; mt < 2; ++mt) {
#pragma unroll
            for (int half = 0; half < 2; ++half) {
                const int row = r0 + wm * 32 + mt * 16 + (lane >> 2) + half * 8;
                const int b = row >> 10, j = row & 1023;
                const bool has = (j + 1) < QL;
                float dot = 0.f;
                float vals[8][2];
#pragma unroll
                for (int nt = 0; nt < 8; ++nt) {
                    float v0 = acc[mt][nt][half * 2 + 0];
                    float v1 = acc[mt][nt][half * 2 + 1];
                    if (mat == 1) {
                        dot += rwv[nt][0] * v0 + rwv[nt][1] * v1;
                        const int d = nt * 8 + 2 * (lane & 3);
                        float2 re = has
                            ? *(const float2*)(remb + ((size_t)(j + 1) * NHEAD + n) * DH + d)
                            : make_float2(0.f, 0.f);
                        v0 += re.x; v1 += re.y;
                    }
                    vals[nt][0] = v0; vals[nt][1] = v1;
                }
                const size_t base =
                    ((size_t)(b * NHEAD + n) * QL + j) * DH + 2 * (lane & 3);
                if (mat == 1) {
#pragma unroll
                    for (int nt = 0; nt < 8; ++nt) {
                        __half2 h2 = __floats2half2_rn(vals[nt][0], vals[nt][1]);
                        *(__half2*)(Cbh + base + nt * 8) = h2;
                        *(__half2*)(Cbl + base + nt * 8) = __floats2half2_rn(
                            vals[nt][0] - __half2float(h2.x),
                            vals[nt][1] - __half2float(h2.y));
                    }
                    dot += __shfl_xor_sync(0xffffffffu, dot, 1);
                    dot += __shfl_xor_sync(0xffffffffu, dot, 2);
                    if ((lane & 3) == 0)
                        tsg[(size_t)(b * NHEAD + n) * QL + j] =
                            dot + (has ? rbias[(size_t)(j + 1) * NHEAD + n] : 0.f);
                } else {
#pragma unroll
                    for (int nt = 0; nt < 8; ++nt)
                        *(__half2*)(Vbh + base + nt * 8) =
                            __floats2half2_rn(vals[nt][0], vals[nt][1]);
                }
            }
        }
    }
}

// ===========================================================================
// Wo GEMM: CTA 64x128, 128 threads, 4 CTAs/SM, single fp16 pass.
// Stage: Ah 4K | Bh 8K = 12KB.
// ===========================================================================
#define STGW 12288
#define SMEM_WO (3 * STGW)

__global__ __launch_bounds__(128, 4) void gemm_wo(
    const __half* __restrict__ Ah, const __half* __restrict__ Bh,
    float* __restrict__ F0)
{
    extern __shared__ char smem[];
    const uint32_t sb = smem_to_u32(smem);
    const int tid = threadIdx.x;
    const int wid = tid >> 5, lane = tid & 31;
    const int wm = wid >> 1, wn = wid & 1;
    const int c0 = blockIdx.x * 128;
    const int r0 = blockIdx.y * 64;

    const char* AgH = (const char*)(Ah + (size_t)r0 * GK);
    const char* BgH = (const char*)(Bh + (size_t)c0 * GK);

    auto load_stage = [&](int st, int ck) {
        const uint32_t s0 = sb + st * STGW;
        const size_t gofs = (size_t)ck * 64;
#pragma unroll
        for (int h = 0; h < 2; ++h) {
            int idx = h * 128 + tid;
            int row = idx >> 2, ch = idx & 3;
            uint32_t o = SW64(row, ch);
            CP_ASYNC16(s0 + o, AgH + (size_t)row * 2048 + gofs + ch * 16);
        }
#pragma unroll
        for (int h = 0; h < 4; ++h) {
            int idx = h * 128 + tid;
            int row = idx >> 2, ch = idx & 3;
            uint32_t o = SW64(row, ch);
            CP_ASYNC16(s0 + 4096 + o, BgH + (size_t)row * 2048 + gofs + ch * 16);
        }
    };

    load_stage(0, 0); CP_ASYNC_COMMIT();
    load_stage(1, 1); CP_ASYNC_COMMIT();

    float acc[2][8][4];
#pragma unroll
    for (int mt = 0; mt < 2; ++mt)
#pragma unroll
        for (int nt = 0; nt < 8; ++nt)
#pragma unroll
            for (int r = 0; r < 4; ++r) acc[mt][nt][r] = 0.f;

    const int sub = lane >> 3, l7 = lane & 7;

    for (int i = 0; i < NCH; ++i) {
        CP_ASYNC_WAIT1();
        __syncthreads();
        if (i + 2 < NCH) load_stage((i + 2) % 3, i + 2);
        CP_ASYNC_COMMIT();

        const uint32_t sA = sb + (i % 3) * STGW;
        const uint32_t sB = sA + 4096;

#pragma unroll
        for (int ks = 0; ks < 2; ++ks) {
            uint32_t ah[2][4];
#pragma unroll
            for (int mt = 0; mt < 2; ++mt) {
                int row = wm * 32 + mt * 16 + ((sub & 1) << 3) + l7;
                int ch = 2 * ks + (sub >> 1);
                uint32_t off = SW64(row, ch);
                LDSM4(ah[mt][0], ah[mt][1], ah[mt][2], ah[mt][3], sA + off);
            }
#pragma unroll
            for (int ntp = 0; ntp < 4; ++ntp) {
                int row = wn * 64 + ntp * 16 + ((sub >> 1) << 3) + l7;
                int ch = 2 * ks + (sub & 1);
                uint32_t off = SW64(row, ch);
                uint32_t bh2[2][2];
                LDSM4(bh2[0][0], bh2[0][1], bh2[1][0], bh2[1][1], sB + off);
#pragma unroll
                for (int h = 0; h < 2; ++h) {
                    const int nt = 2 * ntp + h;
#pragma unroll
                    for (int mt = 0; mt < 2; ++mt)
                        MMA_F16(acc[mt][nt], ah[mt], bh2[h]);
                }
            }
        }
    }

#pragma unroll
    for (int mt = 0; mt < 2; ++mt)
#pragma unroll
        for (int nt = 0; nt < 8; ++nt) {
            int row = r0 + wm * 32 + mt * 16 + (lane >> 2);
            int col = c0 + wn * 64 + nt * 8 + 2 * (lane & 3);
            *(float2*)(F0 + (size_t)row * DM + col) =
                make_float2(acc[mt][nt][0], acc[mt][nt][1]);
            *(float2*)(F0 + (size_t)(row + 8) * DM + col) =
                make_float2(acc[mt][nt][2], acc[mt][nt][3]);
        }
}

// ===========================================================================
// MMA flash attention: 64-query tile, 128 threads, 3 CTAs/SM, 3-STAGE pipeline.
// S = fp16x3. P.V single fp16 pass. Q staged through stage 2.
// Stage: Ch 8K | Cl 8K | Vh 8K | ts 256 = 24832 B. 3 stages = 74496 B.
// ===========================================================================
#define ATT_STG 24832
#define ATT_SMEM (3 * ATT_STG)

__global__ __launch_bounds__(128, 3) void attn_mma(
    const __half* __restrict__ qbh, const __half* __restrict__ qbl,
    const __half* __restrict__ cbh, const __half* __restrict__ cbl,
    const __half* __restrict__ vbh,
    const float* __restrict__ tsg,
    __half* __restrict__ avh)
{
    extern __shared__ char sm[];
    const uint32_t sb = smem_to_u32(sm);

    const int tid = threadIdx.x;
    const int wid = tid >> 5, lane = tid & 31;
    const int sub = lane >> 3, l7 = lane & 7;
    const int i0 = blockIdx.x * 64, n = blockIdx.y, b = blockIdx.z;

    const size_t kvb = ((size_t)(b * NHEAD + n) * QL) * DH * 2;
    const char* chg = (const char*)cbh + kvb;
    const char* clg = (const char*)cbl + kvb;
    const char* vhg = (const char*)vbh + kvb;
    const char* tg = (const char*)(tsg + (size_t)(b * NHEAD + n) * QL);

    // Q -> stage 2 (hi at +0, lo at +8192)
    {
        const uint32_t q0 = sb + 2 * ATT_STG;
        const char* qhg = (const char*)qbh + ((size_t)(b * QL + i0) * DM + n * DH) * 2;
        const char* qlg = (const char*)qbl + ((size_t)(b * QL + i0) * DM + n * DH) * 2;
#pragma unroll
        for (int r = 0; r < 4; ++r) {
            int id = r * 128 + tid;
            int row = id >> 3, ch = id & 7;
            uint32_t o = SWOFF(row, ch);
            CP_ASYNC16(q0 + o, qhg + (size_t)row * 2048 + ch * 16);
            CP_ASYNC16(q0 + 8192 + o, qlg + (size_t)row * 2048 + ch * 16);
        }
        CP_ASYNC_COMMIT();
    }

    auto load_stage = [&](int s, int jt) {
        const uint32_t st = sb + s * ATT_STG;
        const size_t go = (size_t)jt * 64 * 128;
#pragma unroll
        for (int r = 0; r < 4; ++r) {
            int id = r * 128 + tid;
            int row = id >> 3, ch = id & 7;
            uint32_t o = SWOFF(row, ch);
            size_t g = go + (size_t)row * 128 + ch * 16;
            CP_ASYNC16(st + o, chg + g);
            CP_ASYNC16(st + 8192 + o, clg + g);
            CP_ASYNC16(st + 16384 + o, vhg + g);
        }
        if (tid < 16) CP_ASYNC16(st + 24576 + tid * 16, tg + (size_t)jt * 256 + tid * 16);
    };

    load_stage(0, 0); CP_ASYNC_COMMIT();
    load_stage(1, 1); CP_ASYNC_COMMIT();

    CP_ASYNC_WAIT2();   // Q resident (kv0, kv1 may pend)
    __syncthreads();

    uint32_t qhf[4][4], qlf[4][4];
    {
        const uint32_t q0 = sb + 2 * ATT_STG;
#pragma unroll
        for (int kc = 0; kc < 4; ++kc) {
            int row = wid * 16 + ((sub & 1) << 3) + l7;
            int ch = 2 * kc + (sub >> 1);
            uint32_t o = SWOFF(row, ch);
            LDSM4(qhf[kc][0], qhf[kc][1], qhf[kc][2], qhf[kc][3], q0 + o);
            LDSM4(qlf[kc][0], qlf[kc][1], qlf[kc][2], qlf[kc][3], q0 + 8192 + o);
        }
    }
    __syncthreads();   // all warps consumed Q; stage 2 free for kv2

    float o_[8][4];
    float m0 = -1e30f, m1 = -1e30f, l0 = 0.f, l1 = 0.f;
#pragma unroll
    for (int t = 0; t < 8; ++t)
#pragma unroll
        for (int r = 0; r < 4; ++r) o_[t][r] = 0.f;

    for (int jt = 0; jt < 16; ++jt) {
        CP_ASYNC_WAIT1();   // kv_jt resident (kv_{jt+1} may pend)
        __syncthreads();

        const uint32_t st = sb + (jt % 3) * ATT_STG;
        const float* tsp = (const float*)(sm + (jt % 3) * ATT_STG + 24576);

        float sc[8][4];
#pragma unroll
        for (int t = 0; t < 8; ++t)
#pragma unroll
            for (int r = 0; r < 4; ++r) sc[t][r] = 0.f;

#pragma unroll
        for (int kc = 0; kc < 4; ++kc) {
#pragma unroll
            for (int p = 0; p < 4; ++p) {
                int row = p * 16 + ((sub >> 1) << 3) + l7;
                int ch = 2 * kc + (sub & 1);
                uint32_t o = SWOFF(row, ch);
                uint32_t bh[2][2], bl[2][2];
                LDSM4(bh[0][0], bh[0][1], bh[1][0], bh[1][1], st + o);
                LDSM4(bl[0][0], bl[0][1], bl[1][0], bl[1][1], st + 8192 + o);
#pragma unroll
                for (int h = 0; h < 2; ++h) {
                    MMA_F16(sc[2 * p + h], qhf[kc], bh[h]);
                    MMA_F16(sc[2 * p + h], qhf[kc], bl[h]);
                    MMA_F16(sc[2 * p + h], qlf[kc], bh[h]);
                }
            }
        }

#pragma unroll
        for (int t = 0; t < 8; ++t) {
            float2 tv = *(const float2*)(tsp + t * 8 + (lane & 3) * 2);
            sc[t][0] = (sc[t][0] + tv.x) * 0.125f;
            sc[t][1] = (sc[t][1] + tv.y) * 0.125f;
            sc[t][2] = (sc[t][2] + tv.x) * 0.125f;
            sc[t][3] = (sc[t][3] + tv.y) * 0.125f;
        }

        float mx0 = -1e30f, mx1 = -1e30f;
#pragma unroll
        for (int t = 0; t < 8; ++t) {
            mx0 = fmaxf(mx0, fmaxf(sc[t][0], sc[t][1]));
            mx1 = fmaxf(mx1, fmaxf(sc[t][2], sc[t][3]));
        }
        mx0 = fmaxf(mx0, __shfl_xor_sync(0xffffffffu, mx0, 1));
        mx0 = fmaxf(mx0, __shfl_xor_sync(0xffffffffu, mx0, 2));
        mx1 = fmaxf(mx1, __shfl_xor_sync(0xffffffffu, mx1, 1));
        mx1 = fmaxf(mx1, __shfl_xor_sync(0xffffffffu, mx1, 2));
        const float nm0 = fmaxf(m0, mx0), nm1 = fmaxf(m1, mx1);
        const float a0 = __expf(m0 - nm0), a1 = __expf(m1 - nm1);
        m0 = nm0; m1 = nm1;

        float sum0 = 0.f, sum1 = 0.f;
#pragma unroll
        for (int t = 0; t < 8; ++t) {
            sc[t][0] = __expf(sc[t][0] - nm0);
            sc[t][1] = __expf(sc[t][1] - nm0);
            sc[t][2] = __expf(sc[t][2] - nm1);
            sc[t][3] = __expf(sc[t][3] - nm1);
            sum0 += sc[t][0] + sc[t][1];
            sum1 += sc[t][2] + sc[t][3];
        }
        sum0 += __shfl_xor_sync(0xffffffffu, sum0, 1);
        sum0 += __shfl_xor_sync(0xffffffffu, sum0, 2);
        sum1 += __shfl_xor_sync(0xffffffffu, sum1, 1);
        sum1 += __shfl_xor_sync(0xffffffffu, sum1, 2);
        l0 = l0 * a0 + sum0;
        l1 = l1 * a1 + sum1;
#pragma unroll
        for (int t = 0; t < 8; ++t) {
            o_[t][0] *= a0; o_[t][1] *= a0;
            o_[t][2] *= a1; o_[t][3] *= a1;
        }

#pragma unroll
        for (int kc = 0; kc < 4; ++kc) {
            uint32_t ah[4];
#pragma unroll
            for (int h = 0; h < 2; ++h) {
                const int t = 2 * kc + h;
                __half2 p01 = __floats2half2_rn(sc[t][0], sc[t][1]);
                __half2 p23 = __floats2half2_rn(sc[t][2], sc[t][3]);
                ah[2 * h + 0] = *(uint32_t*)&p01;
                ah[2 * h + 1] = *(uint32_t*)&p23;
            }
#pragma unroll
            for (int g = 0; g < 4; ++g) {
                int row = 16 * kc + ((sub & 1) << 3) + l7;
                int ch = 2 * g + (sub >> 1);
                uint32_t o = SWOFF(row, ch);
                uint32_t vh[2][2];
                LDSM4T(vh[0][0], vh[0][1], vh[1][0], vh[1][1], st + 16384 + o);
#pragma unroll
                for (int h = 0; h < 2; ++h)
                    MMA_F16(o_[2 * g + h], ah, vh[h]);
            }
        }

        __syncthreads();
        if (jt + 2 < 16) load_stage((jt + 2) % 3, jt + 2);
        CP_ASYNC_COMMIT();
    }

    const float inv0 = 1.f / l0, inv1 = 1.f / l1;
    const int row0 = i0 + wid * 16 + (lane >> 2);
#pragma unroll
    for (int t = 0; t < 8; ++t) {
        const int col = n * DH + t * 8 + (lane & 3) * 2;
        float v0 = o_[t][0] * inv0, v1 = o_[t][1] * inv0;
        float v2 = o_[t][2] * inv1, v3 = o_[t][3] * inv1;
        size_t p0 = (size_t)(b * QL + row0) * DM + col;
        size_t p1 = (size_t)(b * QL + row0 + 8) * DM + col;
        *(__half2*)(avh + p0) = __floats2half2_rn(v0, v1);
        *(__half2*)(avh + p1) = __floats2half2_rn(v2, v3);
    }
}

// ===========================================================================
// Residual + LayerNorm
// ===========================================================================
__global__ __launch_bounds__(256) void ln_kernel(
    const float* __restrict__ w, const float* __restrict__ ao,
    const float* __restrict__ gamma, const float* __restrict__ beta,
    float* __restrict__ out)
{
    __shared__ float ssum[8], ssq[8];
    const int row = blockIdx.x;
    const int tid = threadIdx.x;
    const size_t base = (size_t)row * DM + tid * 4;

    float4 x = *(const float4*)(w + base);
    float4 a = *(const float4*)(ao + base);
    x.x += a.x; x.y += a.y; x.z += a.z; x.w += a.w;

    float sum = x.x + x.y + x.z + x.w;
    float sq = x.x * x.x + x.y * x.y + x.z * x.z + x.w * x.w;
#pragma unroll
    for (int off = 16; off; off >>= 1) {
        sum += __shfl_xor_sync(0xffffffffu, sum, off);
        sq += __shfl_xor_sync(0xffffffffu, sq, off);
    }
    const int wid = tid >> 5;
    if ((tid & 31) == 0) { ssum[wid] = sum; ssq[wid] = sq; }
    __syncthreads();
    sum = 0.f; sq = 0.f;
#pragma unroll
    for (int i = 0; i < 8; ++i) { sum += ssum[i]; sq += ssq[i]; }

    const float mu = sum * (1.f / DM);
    const float var = sq * (1.f / DM) - mu * mu;
    const float inv = rsqrtf(var + 1e-5f);

    float4 g = *(const float4*)(gamma + (size_t)tid * 4);
    float4 be = *(const float4*)(beta + (size_t)tid * 4);
    float4 r;
    r.x = (x.x - mu) * inv * g.x + be.x;
    r.y = (x.y - mu) * inv * g.y + be.y;
    r.z = (x.z - mu) * inv * g.z + be.z;
    r.w = (x.w - mu) * inv * g.w + be.w;
    *(float4*)(out + base) = r;
}

// ===========================================================================
extern "C" void kernel_launch(void* const* d_in, const int* in_sizes, int n_in,
                              void* d_out, int out_size)
{
    (void)in_sizes; (void)n_in; (void)out_size;
    const float* w      = (const float*)d_in[0];
    const float* r_emb  = (const float*)d_in[1];
    const float* r_w_b  = (const float*)d_in[2];
    const float* r_bias = (const float*)d_in[3];
    const float* Wq     = (const float*)d_in[4];
    const float* Wk     = (const float*)d_in[5];
    const float* Wv     = (const float*)d_in[6];
    const float* Wo     = (const float*)d_in[7];
    const float* gamma  = (const float*)d_in[8];
    const float* beta   = (const float*)d_in[9];
    float* out = (float*)d_out;

    float *ao, *tsg;
    __half *wh, *wl, *avh, *bh, *bl;
    __half *qbh, *qbl, *cbh, *cbl, *vbh;
    cudaGetSymbolAddress((void**)&ao, g_ao);
    cudaGetSymbolAddress((void**)&wh, g_wh);
    cudaGetSymbolAddress((void**)&wl, g_wl);
    cudaGetSymbolAddress((void**)&avh, g_avh);
    cudaGetSymbolAddress((void**)&bh, g_bh);
    cudaGetSymbolAddress((void**)&bl, g_bl);
    cudaGetSymbolAddress((void**)&qbh, g_qbh);
    cudaGetSymbolAddress((void**)&qbl, g_qbl);
    cudaGetSymbolAddress((void**)&cbh, g_cbh);
    cudaGetSymbolAddress((void**)&cbl, g_cbl);
    cudaGetSymbolAddress((void**)&vbh, g_vbh);
    cudaGetSymbolAddress((void**)&tsg, g_ts);

    prep_all<<<dim3(32, 32, 8), 256>>>(w, Wq, Wk, Wv, Wo, wh, wl, bh, bl);

    cudaFuncSetAttribute(gemm_qkv,
                         cudaFuncAttributeMaxDynamicSharedMemorySize, SMEM_G64);
    gemm_qkv<<<dim3(24, 64), 128, SMEM_G64>>>(
        wh, wl, bh, bl, r_emb, r_w_b, r_bias,
        qbh, qbl, cbh, cbl, vbh, tsg);

    cudaFuncSetAttribute(attn_mma,
                         cudaFuncAttributeMaxDynamicSharedMemorySize, ATT_SMEM);
    attn_mma<<<dim3(QL / 64, NHEAD, BB), 128, ATT_SMEM>>>(
        qbh, qbl, cbh, cbl, vbh, tsg, avh);

    cudaFuncSetAttribute(gemm_wo,
                         cudaFuncAttributeMaxDynamicSharedMemorySize, SMEM_WO);
    gemm_wo<<<dim3(8, 64), 128, SMEM_WO>>>(
        avh, bh + 3 * (size_t)DM * DM, ao);

    ln_kernel<<<MTOT, 256>>>(w, ao, gamma, beta, out);
}

// round 14
// speedup vs baseline: 1.0727x; 1.0727x over previous
#include <cuda_runtime.h>
#include <cuda_fp16.h>
#include <cstdint>

#define BB 4
#define QL 1024
#define DM 1024
#define NHEAD 16
#define DH 64
#define MTOT (BB * QL)  // 4096

// fp32 scratch
__device__ float g_ao[(size_t)MTOT * DM];
// fp16 split operands
__device__ __half g_wh[(size_t)MTOT * DM];
__device__ __half g_wl[(size_t)MTOT * DM];
__device__ __half g_avh[(size_t)MTOT * DM];
__device__ __half g_bh[(size_t)4 * DM * DM];
__device__ __half g_bl[(size_t)4 * DM * DM];
// attention operands
__device__ __half g_qbh[(size_t)MTOT * DM];
__device__ __half g_qbl[(size_t)MTOT * DM];
__device__ __half g_cbh[(size_t)BB * NHEAD * QL * DH];
__device__ __half g_cbl[(size_t)BB * NHEAD * QL * DH];
__device__ __half g_vbh[(size_t)BB * NHEAD * QL * DH];
__device__ float g_ts[(size_t)BB * NHEAD * QL];

// ===========================================================================
// PTX helpers (portable sm_80/90-class only)
// ===========================================================================
__device__ __forceinline__ uint32_t smem_to_u32(const void* p) {
    uint32_t a;
    asm("{ .reg .u64 t; cvta.to.shared.u64 t, %1; cvt.u32.u64 %0, t; }"
        : "=r"(a) : "l"(p));
    return a;
}
#define CP_ASYNC16(s, g) \
    asm volatile("cp.async.cg.shared.global [%0], [%1], 16;" :: "r"(s), "l"(g) : "memory")
#define CP_ASYNC_COMMIT() asm volatile("cp.async.commit_group;" ::: "memory")
#define CP_ASYNC_WAIT1() asm volatile("cp.async.wait_group 1;" ::: "memory")
#define CP_ASYNC_WAIT2() asm volatile("cp.async.wait_group 2;" ::: "memory")

#define LDSM4(r0, r1, r2, r3, addr)                                            \
    asm volatile("ldmatrix.sync.aligned.m8n8.x4.shared.b16 {%0,%1,%2,%3}, [%4];" \
                 : "=r"(r0), "=r"(r1), "=r"(r2), "=r"(r3) : "r"(addr))
#define LDSM4T(r0, r1, r2, r3, addr)                                           \
    asm volatile("ldmatrix.sync.aligned.m8n8.x4.trans.shared.b16 {%0,%1,%2,%3}, [%4];" \
                 : "=r"(r0), "=r"(r1), "=r"(r2), "=r"(r3) : "r"(addr))

#define MMA_F16(d, a, b)                                                       \
    asm volatile("mma.sync.aligned.m16n8k16.row.col.f32.f16.f16.f32 "          \
                 "{%0,%1,%2,%3}, {%4,%5,%6,%7}, {%8,%9}, {%0,%1,%2,%3};"       \
                 : "+f"((d)[0]), "+f"((d)[1]), "+f"((d)[2]), "+f"((d)[3])      \
                 : "r"((a)[0]), "r"((a)[1]), "r"((a)[2]), "r"((a)[3]),         \
                   "r"((b)[0]), "r"((b)[1]))

// 64B rows (32 fp16), 4x16B chunks
#define SW64(row, ch) ((row) * 64 + (((ch) ^ (((row) >> 1) & 3)) << 4))
// 128B rows (64 fp16), 8x16B chunks
#define SWOFF(row, ch) ((row) * 128 + (((ch) ^ ((row) & 7)) << 4))

// ===========================================================================
// prep_all: z<4 -> weight transpose+split; z>=4 -> activation split (fp16)
// ===========================================================================
__global__ __launch_bounds__(256) void prep_all(
    const float* __restrict__ w,
    const float* __restrict__ s0, const float* __restrict__ s1,
    const float* __restrict__ s2, const float* __restrict__ s3,
    __half* __restrict__ wh, __half* __restrict__ wl,
    __half* __restrict__ bh, __half* __restrict__ bl)
{
    const int z = blockIdx.z;
    if (z >= 4) {
        int i = (((z - 4) * 32 + blockIdx.y) * 32 + blockIdx.x) * 256 + threadIdx.x;
        float4 a = ((const float4*)w)[i];
        __half h0 = __float2half_rn(a.x), h1 = __float2half_rn(a.y);
        __half h2 = __float2half_rn(a.z), h3 = __float2half_rn(a.w);
        ((__half2*)wh)[i * 2 + 0] = __halves2half2(h0, h1);
        ((__half2*)wh)[i * 2 + 1] = __halves2half2(h2, h3);
        ((__half2*)wl)[i * 2 + 0] = __halves2half2(
            __float2half_rn(a.x - __half2float(h0)),
            __float2half_rn(a.y - __half2float(h1)));
        ((__half2*)wl)[i * 2 + 1] = __halves2half2(
            __float2half_rn(a.z - __half2float(h2)),
            __float2half_rn(a.w - __half2float(h3)));
        return;
    }
    __shared__ float t[32][33];
    const float* S = z == 0 ? s0 : z == 1 ? s1 : z == 2 ? s2 : s3;
    __half* H = bh + (size_t)z * DM * DM;
    __half* L = bl + (size_t)z * DM * DM;
    const int x = blockIdx.x * 32, y = blockIdx.y * 32;
    const int tx = threadIdx.x & 31, ty = threadIdx.x >> 5;
#pragma unroll
    for (int i = 0; i < 32; i += 8)
        t[ty + i][tx] = S[(size_t)(y + ty + i) * DM + x + tx];
    __syncthreads();
    const int c = (threadIdx.x & 15) * 2;
    const int rb = threadIdx.x >> 4;
#pragma unroll
    for (int i = 0; i < 32; i += 16) {
        const int r = rb + i;
        float a0 = t[c][r], a1 = t[c + 1][r];
        __half h0 = __float2half_rn(a0), h1 = __float2half_rn(a1);
        size_t idx = (size_t)(x + r) * DM + y + c;
        *(__half2*)(H + idx) = __halves2half2(h0, h1);
        *(__half2*)(L + idx) = __halves2half2(
            __float2half_rn(a0 - __half2float(h0)),
            __float2half_rn(a1 - __half2float(h1)));
    }
}

// ===========================================================================
// QKV GEMM: CTA 64x128, 128 threads, 3 CTAs/SM.
// Grid (8, 192): mat = blockIdx.y >> 6 (homogeneous waves; cheap V CTAs last).
// mat 0 (Q), 1 (K->C + ts): fp16x3. mat 2 (V): fp16 single pass.
// ===========================================================================
#define GK 1024
#define NCH 32
#define STG3 24576
#define SMEM_G64 (3 * STG3)

__global__ __launch_bounds__(128, 3) void gemm_qkv(
    const __half* __restrict__ Ah, const __half* __restrict__ Al,
    const __half* __restrict__ Bh, const __half* __restrict__ Bl,
    const float* __restrict__ remb, const float* __restrict__ rwb,
    const float* __restrict__ rbias,
    __half* __restrict__ Qh, __half* __restrict__ Ql,
    __half* __restrict__ Cbh, __half* __restrict__ Cbl,
    __half* __restrict__ Vbh,
    float* __restrict__ tsg)
{
    extern __shared__ char smem[];
    const uint32_t sb = smem_to_u32(smem);
    const int tid = threadIdx.x;
    const int wid = tid >> 5, lane = tid & 31;
    const int wm = wid >> 1, wn = wid & 1;
    const int mat = blockIdx.y >> 6;
    const int c0 = blockIdx.x * 128;
    const int r0 = (blockIdx.y & 63) * 64;
    const bool third = (mat != 2);

    const char* AgH = (const char*)(Ah + (size_t)r0 * GK);
    const char* AgL = (const char*)(Al + (size_t)r0 * GK);
    const char* BgH = (const char*)(Bh + (size_t)mat * DM * DM + (size_t)c0 * GK);
    const char* BgL = (const char*)(Bl + (size_t)mat * DM * DM + (size_t)c0 * GK);

    auto load_stage = [&](int st, int ck) {
        const uint32_t s0 = sb + st * STG3;
        const size_t gofs = (size_t)ck * 64;
#pragma unroll
        for (int h = 0; h < 2; ++h) {
            int idx = h * 128 + tid;
            int row = idx >> 2, ch = idx & 3;
            uint32_t o = SW64(row, ch);
            size_t g = (size_t)row * 2048 + gofs + ch * 16;
            CP_ASYNC16(s0 + o, AgH + g);
            if (third) CP_ASYNC16(s0 + 4096 + o, AgL + g);
        }
#pragma unroll
        for (int h = 0; h < 4; ++h) {
            int idx = h * 128 + tid;
            int row = idx >> 2, ch = idx & 3;
            uint32_t o = SW64(row, ch);
            size_t g = (size_t)row * 2048 + gofs + ch * 16;
            CP_ASYNC16(s0 + 8192 + o, BgH + g);
            if (third) CP_ASYNC16(s0 + 16384 + o, BgL + g);
        }
    };

    load_stage(0, 0); CP_ASYNC_COMMIT();
    load_stage(1, 1); CP_ASYNC_COMMIT();

    float acc[2][8][4];
#pragma unroll
    for (int mt = 0; mt < 2; ++mt)
#pragma unroll
        for (int nt = 0; nt < 8; ++nt)
#pragma unroll
            for (int r = 0; r < 4; ++r) acc[mt][nt][r] = 0.f;

    const int sub = lane >> 3, l7 = lane & 7;

    for (int i = 0; i < NCH; ++i) {
        CP_ASYNC_WAIT1();
        __syncthreads();
        if (i + 2 < NCH) load_stage((i + 2) % 3, i + 2);
        CP_ASYNC_COMMIT();

        const uint32_t sA = sb + (i % 3) * STG3;
        const uint32_t sB = sA + 8192;

#pragma unroll
        for (int ks = 0; ks < 2; ++ks) {
            uint32_t ah[2][4], al[2][4], bh2[4][2][2], bl2[4][2][2];
#pragma unroll
            for (int mt = 0; mt < 2; ++mt) {
                int row = wm * 32 + mt * 16 + ((sub & 1) << 3) + l7;
                int ch = 2 * ks + (sub >> 1);
                uint32_t off = SW64(row, ch);
                LDSM4(ah[mt][0], ah[mt][1], ah[mt][2], ah[mt][3], sA + off);
                if (third)
                    LDSM4(al[mt][0], al[mt][1], al[mt][2], al[mt][3],
                          sA + 4096 + off);
            }
#pragma unroll
            for (int ntp = 0; ntp < 4; ++ntp) {
                int row = wn * 64 + ntp * 16 + ((sub >> 1) << 3) + l7;
                int ch = 2 * ks + (sub & 1);
                uint32_t off = SW64(row, ch);
                LDSM4(bh2[ntp][0][0], bh2[ntp][0][1], bh2[ntp][1][0],
                      bh2[ntp][1][1], sB + off);
                if (third)
                    LDSM4(bl2[ntp][0][0], bl2[ntp][0][1], bl2[ntp][1][0],
                          bl2[ntp][1][1], sB + 8192 + off);
            }
#pragma unroll
            for (int ntp = 0; ntp < 4; ++ntp)
#pragma unroll
                for (int h = 0; h < 2; ++h)
#pragma unroll
                    for (int mt = 0; mt < 2; ++mt)
                        MMA_F16(acc[mt][2 * ntp + h], ah[mt], bh2[ntp][h]);
            if (third) {
#pragma unroll
                for (int ntp = 0; ntp < 4; ++ntp)
#pragma unroll
                    for (int h = 0; h < 2; ++h)
#pragma unroll
                        for (int mt = 0; mt < 2; ++mt) {
                            MMA_F16(acc[mt][2 * ntp + h], ah[mt], bl2[ntp][h]);
                            MMA_F16(acc[mt][2 * ntp + h], al[mt], bh2[ntp][h]);
                        }
            }
        }
    }

    if (mat == 0) {
#pragma unroll
        for (int mt = 0; mt < 2; ++mt)
#pragma unroll
            for (int nt = 0; nt < 8; ++nt) {
                int row = r0 + wm * 32 + mt * 16 + (lane >> 2);
                int col = c0 + wn * 64 + nt * 8 + 2 * (lane & 3);
                size_t p0 = (size_t)row * DM + col;
                size_t p1 = (size_t)(row + 8) * DM + col;
                float v0 = acc[mt][nt][0], v1 = acc[mt][nt][1];
                float v2 = acc[mt][nt][2], v3 = acc[mt][nt][3];
                __half2 h01 = __floats2half2_rn(v0, v1);
                __half2 h23 = __floats2half2_rn(v2, v3);
                *(__half2*)(Qh + p0) = h01;
                *(__half2*)(Qh + p1) = h23;
                *(__half2*)(Ql + p0) = __floats2half2_rn(
                    v0 - __half2float(h01.x), v1 - __half2float(h01.y));
                *(__half2*)(Ql + p1) = __floats2half2_rn(
                    v2 - __half2float(h23.x), v3 - __half2float(h23.y));
            }
    } else {
        const int n = (blockIdx.x << 1) + wn;
        float rwv[8][2];
        if (mat == 1) {
#pragma unroll
            for (int nt = 0; nt < 8; ++nt) {
                float2 t = *(const float2*)(rwb + n * DH + nt * 8 + 2 * (lane & 3));
                rwv[nt][0] = t.x; rwv[nt][1] = t.y;
            }
        }
#pragma unroll
        for (int mt = 0; mt < 2; ++mt) {
#pragma unroll
            for (int half = 0; half < 2; ++half) {
                const int row = r0 + wm * 32 + mt * 16 + (lane >> 2) + half * 8;
                const int b = row >> 10, j = row & 1023;
                const bool has = (j + 1) < QL;
                float dot = 0.f;
                float vals[8][2];
#pragma unroll
                for (int nt = 0; nt < 8; ++nt) {
                    float v0 = acc[mt][nt][half * 2 + 0];
                    float v1 = acc[mt][nt][half * 2 + 1];
                    if (mat == 1) {
                        dot += rwv[nt][0] * v0 + rwv[nt][1] * v1;
                        const int d = nt * 8 + 2 * (lane & 3);
                        float2 re = has
                            ? *(const float2*)(remb + ((size_t)(j + 1) * NHEAD + n) * DH + d)
                            : make_float2(0.f, 0.f);
                        v0 += re.x; v1 += re.y;
                    }
                    vals[nt][0] = v0; vals[nt][1] = v1;
                }
                const size_t base =
                    ((size_t)(b * NHEAD + n) * QL + j) * DH + 2 * (lane & 3);
                if (mat == 1) {
#pragma unroll
                    for (int nt = 0; nt < 8; ++nt) {
                        __half2 h2 = __floats2half2_rn(vals[nt][0], vals[nt][1]);
                        *(__half2*)(Cbh + base + nt * 8) = h2;
                        *(__half2*)(Cbl + base + nt * 8) = __floats2half2_rn(
                            vals[nt][0] - __half2float(h2.x),
                            vals[nt][1] - __half2float(h2.y));
                    }
                    dot += __shfl_xor_sync(0xffffffffu, dot, 1);
                    dot += __shfl_xor_sync(0xffffffffu, dot, 2);
                    if ((lane & 3) == 0)
                        tsg[(size_t)(b * NHEAD + n) * QL + j] =
                            dot + (has ? rbias[(size_t)(j + 1) * NHEAD + n] : 0.f);
                } else {
#pragma unroll
                    for (int nt = 0; nt < 8; ++nt)
                        *(__half2*)(Vbh + base + nt * 8) =
                            __floats2half2_rn(vals[nt][0], vals[nt][1]);
                }
            }
        }
    }
}

// ===========================================================================
// Wo GEMM: CTA 128x128, 256 threads, 2 CTAs/SM, single fp16 pass, 4 STAGES.
// Stage: Ah 8K | Bh 8K = 16KB. 4 stages = 64KB.
// ===========================================================================
#define STGW 16384
#define SMEM_WO (4 * STGW)

__global__ __launch_bounds__(256, 2) void gemm_wo(
    const __half* __restrict__ Ah, const __half* __restrict__ Bh,
    float* __restrict__ F0)
{
    extern __shared__ char smem[];
    const uint32_t sb = smem_to_u32(smem);
    const int tid = threadIdx.x;
    const int wid = tid >> 5, lane = tid & 31;
    const int wm = wid >> 1, wn = wid & 1;
    const int c0 = blockIdx.x * 128;
    const int r0 = blockIdx.y * 128;

    const char* AgH = (const char*)(Ah + (size_t)r0 * GK);
    const char* BgH = (const char*)(Bh + (size_t)c0 * GK);

    auto load_stage = [&](int st, int ck) {
        const uint32_t s0 = sb + st * STGW;
        const size_t gofs = (size_t)ck * 64;
#pragma unroll
        for (int h = 0; h < 2; ++h) {
            int idx = h * 256 + tid;
            int row = idx >> 2, ch = idx & 3;
            uint32_t o = SW64(row, ch);
            size_t g = (size_t)row * 2048 + gofs + ch * 16;
            CP_ASYNC16(s0 + o, AgH + g);
            CP_ASYNC16(s0 + 8192 + o, BgH + g);
        }
    };

    load_stage(0, 0); CP_ASYNC_COMMIT();
    load_stage(1, 1); CP_ASYNC_COMMIT();
    load_stage(2, 2); CP_ASYNC_COMMIT();

    float acc[2][8][4];
#pragma unroll
    for (int mt = 0; mt < 2; ++mt)
#pragma unroll
        for (int nt = 0; nt < 8; ++nt)
#pragma unroll
            for (int r = 0; r < 4; ++r) acc[mt][nt][r] = 0.f;

    const int sub = lane >> 3, l7 = lane & 7;

    for (int i = 0; i < NCH; ++i) {
        CP_ASYNC_WAIT2();   // chunk i resident; i+1, i+2 may pend
        __syncthreads();
        if (i + 3 < NCH) load_stage((i + 3) & 3, i + 3);
        CP_ASYNC_COMMIT();

        const uint32_t sA = sb + (i & 3) * STGW;
        const uint32_t sB = sA + 8192;

#pragma unroll
        for (int ks = 0; ks < 2; ++ks) {
            uint32_t ah[2][4];
#pragma unroll
            for (int mt = 0; mt < 2; ++mt) {
                int row = wm * 32 + mt * 16 + ((sub & 1) << 3) + l7;
                int ch = 2 * ks + (sub >> 1);
                uint32_t off = SW64(row, ch);
                LDSM4(ah[mt][0], ah[mt][1], ah[mt][2], ah[mt][3], sA + off);
            }
#pragma unroll
            for (int ntp = 0; ntp < 4; ++ntp) {
                int row = wn * 64 + ntp * 16 + ((sub >> 1) << 3) + l7;
                int ch = 2 * ks + (sub & 1);
                uint32_t off = SW64(row, ch);
                uint32_t bh2[2][2];
                LDSM4(bh2[0][0], bh2[0][1], bh2[1][0], bh2[1][1], sB + off);
#pragma unroll
                for (int h = 0; h < 2; ++h) {
                    const int nt = 2 * ntp + h;
#pragma unroll
                    for (int mt = 0; mt < 2; ++mt)
                        MMA_F16(acc[mt][nt], ah[mt], bh2[h]);
                }
            }
        }
    }

#pragma unroll
    for (int mt = 0; mt < 2; ++mt)
#pragma unroll
        for (int nt = 0; nt < 8; ++nt) {
            int row = r0 + wm * 32 + mt * 16 + (lane >> 2);
            int col = c0 + wn * 64 + nt * 8 + 2 * (lane & 3);
            *(float2*)(F0 + (size_t)row * DM + col) =
                make_float2(acc[mt][nt][0], acc[mt][nt][1]);
            *(float2*)(F0 + (size_t)(row + 8) * DM + col) =
                make_float2(acc[mt][nt][2], acc[mt][nt][3]);
        }
}

// ===========================================================================
// MMA flash attention: 64-query tile, 128 threads, 3 CTAs/SM (R12 exact).
// S = fp16x3. P.V single fp16 pass. Output AV-hi only.
// Stage: Ch 8K | Cl 8K | Vh 8K | ts 256 = 24832 B.
// ===========================================================================
#define ATT_STG 24832
#define ATT_SMEM (2 * ATT_STG)

__global__ __launch_bounds__(128, 3) void attn_mma(
    const __half* __restrict__ qbh, const __half* __restrict__ qbl,
    const __half* __restrict__ cbh, const __half* __restrict__ cbl,
    const __half* __restrict__ vbh,
    const float* __restrict__ tsg,
    __half* __restrict__ avh)
{
    extern __shared__ char sm[];
    const uint32_t sb = smem_to_u32(sm);

    const int tid = threadIdx.x;
    const int wid = tid >> 5, lane = tid & 31;
    const int sub = lane >> 3, l7 = lane & 7;
    const int i0 = blockIdx.x * 64, n = blockIdx.y, b = blockIdx.z;

    const size_t kvb = ((size_t)(b * NHEAD + n) * QL) * DH * 2;
    const char* chg = (const char*)cbh + kvb;
    const char* clg = (const char*)cbl + kvb;
    const char* vhg = (const char*)vbh + kvb;
    const char* tg = (const char*)(tsg + (size_t)(b * NHEAD + n) * QL);

    {
        const char* qhg = (const char*)qbh + ((size_t)(b * QL + i0) * DM + n * DH) * 2;
        const char* qlg = (const char*)qbl + ((size_t)(b * QL + i0) * DM + n * DH) * 2;
#pragma unroll
        for (int r = 0; r < 4; ++r) {
            int id = r * 128 + tid;
            int row = id >> 3, ch = id & 7;
            uint32_t o = SWOFF(row, ch);
            CP_ASYNC16(sb + o, qhg + (size_t)row * 2048 + ch * 16);
            CP_ASYNC16(sb + 8192 + o, qlg + (size_t)row * 2048 + ch * 16);
        }
        CP_ASYNC_COMMIT();
    }

    auto load_stage = [&](int s, int jt) {
        const uint32_t st = sb + s * ATT_STG;
        const size_t go = (size_t)jt * 64 * 128;
#pragma unroll
        for (int r = 0; r < 4; ++r) {
            int id = r * 128 + tid;
            int row = id >> 3, ch = id & 7;
            uint32_t o = SWOFF(row, ch);
            size_t g = go + (size_t)row * 128 + ch * 16;
            CP_ASYNC16(st + o, chg + g);
            CP_ASYNC16(st + 8192 + o, clg + g);
            CP_ASYNC16(st + 16384 + o, vhg + g);
        }
        if (tid < 16) CP_ASYNC16(st + 24576 + tid * 16, tg + (size_t)jt * 256 + tid * 16);
    };

    load_stage(1, 0); CP_ASYNC_COMMIT();

    CP_ASYNC_WAIT1();
    __syncthreads();

    uint32_t qhf[4][4], qlf[4][4];
#pragma unroll
    for (int kc = 0; kc < 4; ++kc) {
        int row = wid * 16 + ((sub & 1) << 3) + l7;
        int ch = 2 * kc + (sub >> 1);
        uint32_t o = SWOFF(row, ch);
        LDSM4(qhf[kc][0], qhf[kc][1], qhf[kc][2], qhf[kc][3], sb + o);
        LDSM4(qlf[kc][0], qlf[kc][1], qlf[kc][2], qlf[kc][3], sb + 8192 + o);
    }
    __syncthreads();

    load_stage(0, 1); CP_ASYNC_COMMIT();

    float o_[8][4];
    float m0 = -1e30f, m1 = -1e30f, l0 = 0.f, l1 = 0.f;
#pragma unroll
    for (int t = 0; t < 8; ++t)
#pragma unroll
        for (int r = 0; r < 4; ++r) o_[t][r] = 0.f;

    for (int jt = 0; jt < 16; ++jt) {
        CP_ASYNC_WAIT1();
        __syncthreads();

        const int s = (jt + 1) & 1;
        const uint32_t st = sb + s * ATT_STG;
        const float* tsp = (const float*)(sm + s * ATT_STG + 24576);

        float sc[8][4];
#pragma unroll
        for (int t = 0; t < 8; ++t)
#pragma unroll
            for (int r = 0; r < 4; ++r) sc[t][r] = 0.f;

#pragma unroll
        for (int kc = 0; kc < 4; ++kc) {
#pragma unroll
            for (int p = 0; p < 4; ++p) {
                int row = p * 16 + ((sub >> 1) << 3) + l7;
                int ch = 2 * kc + (sub & 1);
                uint32_t o = SWOFF(row, ch);
                uint32_t bh[2][2], bl[2][2];
                LDSM4(bh[0][0], bh[0][1], bh[1][0], bh[1][1], st + o);
                LDSM4(bl[0][0], bl[0][1], bl[1][0], bl[1][1], st + 8192 + o);
#pragma unroll
                for (int h = 0; h < 2; ++h) {
                    MMA_F16(sc[2 * p + h], qhf[kc], bh[h]);
                    MMA_F16(sc[2 * p + h], qhf[kc], bl[h]);
                    MMA_F16(sc[2 * p + h], qlf[kc], bh[h]);
                }
            }
        }

#pragma unroll
        for (int t = 0; t < 8; ++t) {
            float2 tv = *(const float2*)(tsp + t * 8 + (lane & 3) * 2);
            sc[t][0] = (sc[t][0] + tv.x) * 0.125f;
            sc[t][1] = (sc[t][1] + tv.y) * 0.125f;
            sc[t][2] = (sc[t][2] + tv.x) * 0.125f;
            sc[t][3] = (sc[t][3] + tv.y) * 0.125f;
        }

        float mx0 = -1e30f, mx1 = -1e30f;
#pragma unroll
        for (int t = 0; t < 8; ++t) {
            mx0 = fmaxf(mx0, fmaxf(sc[t][0], sc[t][1]));
            mx1 = fmaxf(mx1, fmaxf(sc[t][2], sc[t][3]));
        }
        mx0 = fmaxf(mx0, __shfl_xor_sync(0xffffffffu, mx0, 1));
        mx0 = fmaxf(mx0, __shfl_xor_sync(0xffffffffu, mx0, 2));
        mx1 = fmaxf(mx1, __shfl_xor_sync(0xffffffffu, mx1, 1));
        mx1 = fmaxf(mx1, __shfl_xor_sync(0xffffffffu, mx1, 2));
        const float nm0 = fmaxf(m0, mx0), nm1 = fmaxf(m1, mx1);
        const float a0 = __expf(m0 - nm0), a1 = __expf(m1 - nm1);
        m0 = nm0; m1 = nm1;

        float sum0 = 0.f, sum1 = 0.f;
#pragma unroll
        for (int t = 0; t < 8; ++t) {
            sc[t][0] = __expf(sc[t][0] - nm0);
            sc[t][1] = __expf(sc[t][1] - nm0);
            sc[t][2] = __expf(sc[t][2] - nm1);
            sc[t][3] = __expf(sc[t][3] - nm1);
            sum0 += sc[t][0] + sc[t][1];
            sum1 += sc[t][2] + sc[t][3];
        }
        sum0 += __shfl_xor_sync(0xffffffffu, sum0, 1);
        sum0 += __shfl_xor_sync(0xffffffffu, sum0, 2);
        sum1 += __shfl_xor_sync(0xffffffffu, sum1, 1);
        sum1 += __shfl_xor_sync(0xffffffffu, sum1, 2);
        l0 = l0 * a0 + sum0;
        l1 = l1 * a1 + sum1;
#pragma unroll
        for (int t = 0; t < 8; ++t) {
            o_[t][0] *= a0; o_[t][1] *= a0;
            o_[t][2] *= a1; o_[t][3] *= a1;
        }

#pragma unroll
        for (int kc = 0; kc < 4; ++kc) {
            uint32_t ah[4];
#pragma unroll
            for (int h = 0; h < 2; ++h) {
                const int t = 2 * kc + h;
                __half2 p01 = __floats2half2_rn(sc[t][0], sc[t][1]);
                __half2 p23 = __floats2half2_rn(sc[t][2], sc[t][3]);
                ah[2 * h + 0] = *(uint32_t*)&p01;
                ah[2 * h + 1] = *(uint32_t*)&p23;
            }
#pragma unroll
            for (int g = 0; g < 4; ++g) {
                int row = 16 * kc + ((sub & 1) << 3) + l7;
                int ch = 2 * g + (sub >> 1);
                uint32_t o = SWOFF(row, ch);
                uint32_t vh[2][2];
                LDSM4T(vh[0][0], vh[0][1], vh[1][0], vh[1][1], st + 16384 + o);
#pragma unroll
                for (int h = 0; h < 2; ++h)
                    MMA_F16(o_[2 * g + h], ah, vh[h]);
            }
        }

        __syncthreads();
        if (jt + 2 < 16) load_stage(s, jt + 2);
        CP_ASYNC_COMMIT();
    }

    const float inv0 = 1.f / l0, inv1 = 1.f / l1;
    const int row0 = i0 + wid * 16 + (lane >> 2);
#pragma unroll
    for (int t = 0; t < 8; ++t) {
        const int col = n * DH + t * 8 + (lane & 3) * 2;
        float v0 = o_[t][0] * inv0, v1 = o_[t][1] * inv0;
        float v2 = o_[t][2] * inv1, v3 = o_[t][3] * inv1;
        size_t p0 = (size_t)(b * QL + row0) * DM + col;
        size_t p1 = (size_t)(b * QL + row0 + 8) * DM + col;
        *(__half2*)(avh + p0) = __floats2half2_rn(v0, v1);
        *(__half2*)(avh + p1) = __floats2half2_rn(v2, v3);
    }
}

// ===========================================================================
// Residual + LayerNorm
// ===========================================================================
__global__ __launch_bounds__(256) void ln_kernel(
    const float* __restrict__ w, const float* __restrict__ ao,
    const float* __restrict__ gamma, const float* __restrict__ beta,
    float* __restrict__ out)
{
    __shared__ float ssum[8], ssq[8];
    const int row = blockIdx.x;
    const int tid = threadIdx.x;
    const size_t base = (size_t)row * DM + tid * 4;

    float4 x = *(const float4*)(w + base);
    float4 a = *(const float4*)(ao + base);
    x.x += a.x; x.y += a.y; x.z += a.z; x.w += a.w;

    float sum = x.x + x.y + x.z + x.w;
    float sq = x.x * x.x + x.y * x.y + x.z * x.z + x.w * x.w;
#pragma unroll
    for (int off = 16; off; off >>= 1) {
        sum += __shfl_xor_sync(0xffffffffu, sum, off);
        sq += __shfl_xor_sync(0xffffffffu, sq, off);
    }
    const int wid = tid >> 5;
    if ((tid & 31) == 0) { ssum[wid] = sum; ssq[wid] = sq; }
    __syncthreads();
    sum = 0.f; sq = 0.f;
#pragma unroll
    for (int i = 0; i < 8; ++i) { sum += ssum[i]; sq += ssq[i]; }

    const float mu = sum * (1.f / DM);
    const float var = sq * (1.f / DM) - mu * mu;
    const float inv = rsqrtf(var + 1e-5f);

    float4 g = *(const float4*)(gamma + (size_t)tid * 4);
    float4 be = *(const float4*)(beta + (size_t)tid * 4);
    float4 r;
    r.x = (x.x - mu) * inv * g.x + be.x;
    r.y = (x.y - mu) * inv * g.y + be.y;
    r.z = (x.z - mu) * inv * g.z + be.z;
    r.w = (x.w - mu) * inv * g.w + be.w;
    *(float4*)(out + base) = r;
}

// ===========================================================================
extern "C" void kernel_launch(void* const* d_in, const int* in_sizes, int n_in,
                              void* d_out, int out_size)
{
    (void)in_sizes; (void)n_in; (void)out_size;
    const float* w      = (const float*)d_in[0];
    const float* r_emb  = (const float*)d_in[1];
    const float* r_w_b  = (const float*)d_in[2];
    const float* r_bias = (const float*)d_in[3];
    const float* Wq     = (const float*)d_in[4];
    const float* Wk     = (const float*)d_in[5];
    const float* Wv     = (const float*)d_in[6];
    const float* Wo     = (const float*)d_in[7];
    const float* gamma  = (const float*)d_in[8];
    const float* beta   = (const float*)d_in[9];
    float* out = (float*)d_out;

    float *ao, *tsg;
    __half *wh, *wl, *avh, *bh, *bl;
    __half *qbh, *qbl, *cbh, *cbl, *vbh;
    cudaGetSymbolAddress((void**)&ao, g_ao);
    cudaGetSymbolAddress((void**)&wh, g_wh);
    cudaGetSymbolAddress((void**)&wl, g_wl);
    cudaGetSymbolAddress((void**)&avh, g_avh);
    cudaGetSymbolAddress((void**)&bh, g_bh);
    cudaGetSymbolAddress((void**)&bl, g_bl);
    cudaGetSymbolAddress((void**)&qbh, g_qbh);
    cudaGetSymbolAddress((void**)&qbl, g_qbl);
    cudaGetSymbolAddress((void**)&cbh, g_cbh);
    cudaGetSymbolAddress((void**)&cbl, g_cbl);
    cudaGetSymbolAddress((void**)&vbh, g_vbh);
    cudaGetSymbolAddress((void**)&tsg, g_ts);

    prep_all<<<dim3(32, 32, 8), 256>>>(w, Wq, Wk, Wv, Wo, wh, wl, bh, bl);

    cudaFuncSetAttribute(gemm_qkv,
                         cudaFuncAttributeMaxDynamicSharedMemorySize, SMEM_G64);
    gemm_qkv<<<dim3(8, 192), 128, SMEM_G64>>>(
        wh, wl, bh, bl, r_emb, r_w_b, r_bias,
        qbh, qbl, cbh, cbl, vbh, tsg);

    cudaFuncSetAttribute(attn_mma,
                         cudaFuncAttributeMaxDynamicSharedMemorySize, ATT_SMEM);
    attn_mma<<<dim3(QL / 64, NHEAD, BB), 128, ATT_SMEM>>>(
        qbh, qbl, cbh, cbl, vbh, tsg, avh);

    cudaFuncSetAttribute(gemm_wo,
                         cudaFuncAttributeMaxDynamicSharedMemorySize, SMEM_WO);
    gemm_wo<<<dim3(8, 32), 256, SMEM_WO>>>(
        avh, bh + 3 * (size_t)DM * DM, ao);

    ln_kernel<<<MTOT, 256>>>(w, ao, gamma, beta, out);
}

// round 15
// speedup vs baseline: 1.0779x; 1.0049x over previous
#include <cuda_runtime.h>
#include <cuda_fp16.h>
#include <cstdint>

#define BB 4
#define QL 1024
#define DM 1024
#define NHEAD 16
#define DH 64
#define MTOT (BB * QL)  // 4096

// fp32 scratch
__device__ float g_ao[(size_t)MTOT * DM];
// fp16 split operands
__device__ __half g_wh[(size_t)MTOT * DM];
__device__ __half g_wl[(size_t)MTOT * DM];
__device__ __half g_avh[(size_t)MTOT * DM];
__device__ __half g_bh[(size_t)4 * DM * DM];
__device__ __half g_bl[(size_t)4 * DM * DM];
// attention operands
__device__ __half g_qbh[(size_t)MTOT * DM];
__device__ __half g_qbl[(size_t)MTOT * DM];
__device__ __half g_cbh[(size_t)BB * NHEAD * QL * DH];
__device__ __half g_cbl[(size_t)BB * NHEAD * QL * DH];
__device__ __half g_vbh[(size_t)BB * NHEAD * QL * DH];
__device__ float g_ts[(size_t)BB * NHEAD * QL];

// ===========================================================================
// PTX helpers (portable sm_80/90-class only)
// ===========================================================================
__device__ __forceinline__ uint32_t smem_to_u32(const void* p) {
    uint32_t a;
    asm("{ .reg .u64 t; cvta.to.shared.u64 t, %1; cvt.u32.u64 %0, t; }"
        : "=r"(a) : "l"(p));
    return a;
}
#define CP_ASYNC16(s, g) \
    asm volatile("cp.async.cg.shared.global [%0], [%1], 16;" :: "r"(s), "l"(g) : "memory")
#define CP_ASYNC_COMMIT() asm volatile("cp.async.commit_group;" ::: "memory")
#define CP_ASYNC_WAIT1() asm volatile("cp.async.wait_group 1;" ::: "memory")

#define LDSM4(r0, r1, r2, r3, addr)                                            \
    asm volatile("ldmatrix.sync.aligned.m8n8.x4.shared.b16 {%0,%1,%2,%3}, [%4];" \
                 : "=r"(r0), "=r"(r1), "=r"(r2), "=r"(r3) : "r"(addr))
#define LDSM4T(r0, r1, r2, r3, addr)                                           \
    asm volatile("ldmatrix.sync.aligned.m8n8.x4.trans.shared.b16 {%0,%1,%2,%3}, [%4];" \
                 : "=r"(r0), "=r"(r1), "=r"(r2), "=r"(r3) : "r"(addr))

#define MMA_F16(d, a, b)                                                       \
    asm volatile("mma.sync.aligned.m16n8k16.row.col.f32.f16.f16.f32 "          \
                 "{%0,%1,%2,%3}, {%4,%5,%6,%7}, {%8,%9}, {%0,%1,%2,%3};"       \
                 : "+f"((d)[0]), "+f"((d)[1]), "+f"((d)[2]), "+f"((d)[3])      \
                 : "r"((a)[0]), "r"((a)[1]), "r"((a)[2]), "r"((a)[3]),         \
                   "r"((b)[0]), "r"((b)[1]))

// 64B rows (32 fp16), 4x16B chunks
#define SW64(row, ch) ((row) * 64 + (((ch) ^ (((row) >> 1) & 3)) << 4))
// 128B rows (64 fp16), 8x16B chunks
#define SWOFF(row, ch) ((row) * 128 + (((ch) ^ ((row) & 7)) << 4))

// ===========================================================================
// prep_all: z<4 -> weight transpose+split; z>=4 -> activation split (fp16)
// ===========================================================================
__global__ __launch_bounds__(256) void prep_all(
    const float* __restrict__ w,
    const float* __restrict__ s0, const float* __restrict__ s1,
    const float* __restrict__ s2, const float* __restrict__ s3,
    __half* __restrict__ wh, __half* __restrict__ wl,
    __half* __restrict__ bh, __half* __restrict__ bl)
{
    const int z = blockIdx.z;
    if (z >= 4) {
        int i = (((z - 4) * 32 + blockIdx.y) * 32 + blockIdx.x) * 256 + threadIdx.x;
        float4 a = ((const float4*)w)[i];
        __half h0 = __float2half_rn(a.x), h1 = __float2half_rn(a.y);
        __half h2 = __float2half_rn(a.z), h3 = __float2half_rn(a.w);
        ((__half2*)wh)[i * 2 + 0] = __halves2half2(h0, h1);
        ((__half2*)wh)[i * 2 + 1] = __halves2half2(h2, h3);
        ((__half2*)wl)[i * 2 + 0] = __halves2half2(
            __float2half_rn(a.x - __half2float(h0)),
            __float2half_rn(a.y - __half2float(h1)));
        ((__half2*)wl)[i * 2 + 1] = __halves2half2(
            __float2half_rn(a.z - __half2float(h2)),
            __float2half_rn(a.w - __half2float(h3)));
        return;
    }
    __shared__ float t[32][33];
    const float* S = z == 0 ? s0 : z == 1 ? s1 : z == 2 ? s2 : s3;
    __half* H = bh + (size_t)z * DM * DM;
    __half* L = bl + (size_t)z * DM * DM;
    const int x = blockIdx.x * 32, y = blockIdx.y * 32;
    const int tx = threadIdx.x & 31, ty = threadIdx.x >> 5;
#pragma unroll
    for (int i = 0; i < 32; i += 8)
        t[ty + i][tx] = S[(size_t)(y + ty + i) * DM + x + tx];
    __syncthreads();
    const int c = (threadIdx.x & 15) * 2;
    const int rb = threadIdx.x >> 4;
#pragma unroll
    for (int i = 0; i < 32; i += 16) {
        const int r = rb + i;
        float a0 = t[c][r], a1 = t[c + 1][r];
        __half h0 = __float2half_rn(a0), h1 = __float2half_rn(a1);
        size_t idx = (size_t)(x + r) * DM + y + c;
        *(__half2*)(H + idx) = __halves2half2(h0, h1);
        *(__half2*)(L + idx) = __halves2half2(
            __float2half_rn(a0 - __half2float(h0)),
            __float2half_rn(a1 - __half2float(h1)));
    }
}

// ===========================================================================
// QKV GEMM: CTA 64x128, 128 threads, 3 CTAs/SM, grid (8,192) mat-major (R14).
// mat 0 (Q), 1 (K->C + ts): fp16x3. mat 2 (V): fp16 single pass.
// ===========================================================================
#define GK 1024
#define NCH 32
#define STG3 24576
#define SMEM_G64 (3 * STG3)

__global__ __launch_bounds__(128, 3) void gemm_qkv(
    const __half* __restrict__ Ah, const __half* __restrict__ Al,
    const __half* __restrict__ Bh, const __half* __restrict__ Bl,
    const float* __restrict__ remb, const float* __restrict__ rwb,
    const float* __restrict__ rbias,
    __half* __restrict__ Qh, __half* __restrict__ Ql,
    __half* __restrict__ Cbh, __half* __restrict__ Cbl,
    __half* __restrict__ Vbh,
    float* __restrict__ tsg)
{
    extern __shared__ char smem[];
    const uint32_t sb = smem_to_u32(smem);
    const int tid = threadIdx.x;
    const int wid = tid >> 5, lane = tid & 31;
    const int wm = wid >> 1, wn = wid & 1;
    const int mat = blockIdx.y >> 6;
    const int c0 = blockIdx.x * 128;
    const int r0 = (blockIdx.y & 63) * 64;
    const bool third = (mat != 2);

    const char* AgH = (const char*)(Ah + (size_t)r0 * GK);
    const char* AgL = (const char*)(Al + (size_t)r0 * GK);
    const char* BgH = (const char*)(Bh + (size_t)mat * DM * DM + (size_t)c0 * GK);
    const char* BgL = (const char*)(Bl + (size_t)mat * DM * DM + (size_t)c0 * GK);

    auto load_stage = [&](int st, int ck) {
        const uint32_t s0 = sb + st * STG3;
        const size_t gofs = (size_t)ck * 64;
#pragma unroll
        for (int h = 0; h < 2; ++h) {
            int idx = h * 128 + tid;
            int row = idx >> 2, ch = idx & 3;
            uint32_t o = SW64(row, ch);
            size_t g = (size_t)row * 2048 + gofs + ch * 16;
            CP_ASYNC16(s0 + o, AgH + g);
            if (third) CP_ASYNC16(s0 + 4096 + o, AgL + g);
        }
#pragma unroll
        for (int h = 0; h < 4; ++h) {
            int idx = h * 128 + tid;
            int row = idx >> 2, ch = idx & 3;
            uint32_t o = SW64(row, ch);
            size_t g = (size_t)row * 2048 + gofs + ch * 16;
            CP_ASYNC16(s0 + 8192 + o, BgH + g);
            if (third) CP_ASYNC16(s0 + 16384 + o, BgL + g);
        }
    };

    load_stage(0, 0); CP_ASYNC_COMMIT();
    load_stage(1, 1); CP_ASYNC_COMMIT();

    float acc[2][8][4];
#pragma unroll
    for (int mt = 0; mt < 2; ++mt)
#pragma unroll
        for (int nt = 0; nt < 8; ++nt)
#pragma unroll
            for (int r = 0; r < 4; ++r) acc[mt][nt][r] = 0.f;

    const int sub = lane >> 3, l7 = lane & 7;

    for (int i = 0; i < NCH; ++i) {
        CP_ASYNC_WAIT1();
        __syncthreads();
        if (i + 2 < NCH) load_stage((i + 2) % 3, i + 2);
        CP_ASYNC_COMMIT();

        const uint32_t sA = sb + (i % 3) * STG3;
        const uint32_t sB = sA + 8192;

#pragma unroll
        for (int ks = 0; ks < 2; ++ks) {
            uint32_t ah[2][4], al[2][4], bh2[4][2][2], bl2[4][2][2];
#pragma unroll
            for (int mt = 0; mt < 2; ++mt) {
                int row = wm * 32 + mt * 16 + ((sub & 1) << 3) + l7;
                int ch = 2 * ks + (sub >> 1);
                uint32_t off = SW64(row, ch);
                LDSM4(ah[mt][0], ah[mt][1], ah[mt][2], ah[mt][3], sA + off);
                if (third)
                    LDSM4(al[mt][0], al[mt][1], al[mt][2], al[mt][3],
                          sA + 4096 + off);
            }
#pragma unroll
            for (int ntp = 0; ntp < 4; ++ntp) {
                int row = wn * 64 + ntp * 16 + ((sub >> 1) << 3) + l7;
                int ch = 2 * ks + (sub & 1);
                uint32_t off = SW64(row, ch);
                LDSM4(bh2[ntp][0][0], bh2[ntp][0][1], bh2[ntp][1][0],
                      bh2[ntp][1][1], sB + off);
                if (third)
                    LDSM4(bl2[ntp][0][0], bl2[ntp][0][1], bl2[ntp][1][0],
                          bl2[ntp][1][1], sB + 8192 + off);
            }
#pragma unroll
            for (int ntp = 0; ntp < 4; ++ntp)
#pragma unroll
                for (int h = 0; h < 2; ++h)
#pragma unroll
                    for (int mt = 0; mt < 2; ++mt)
                        MMA_F16(acc[mt][2 * ntp + h], ah[mt], bh2[ntp][h]);
            if (third) {
#pragma unroll
                for (int ntp = 0; ntp < 4; ++ntp)
#pragma unroll
                    for (int h = 0; h < 2; ++h)
#pragma unroll
                        for (int mt = 0; mt < 2; ++mt) {
                            MMA_F16(acc[mt][2 * ntp + h], ah[mt], bl2[ntp][h]);
                            MMA_F16(acc[mt][2 * ntp + h], al[mt], bh2[ntp][h]);
                        }
            }
        }
    }

    if (mat == 0) {
#pragma unroll
        for (int mt = 0; mt < 2; ++mt)
#pragma unroll
            for (int nt = 0; nt < 8; ++nt) {
                int row = r0 + wm * 32 + mt * 16 + (lane >> 2);
                int col = c0 + wn * 64 + nt * 8 + 2 * (lane & 3);
                size_t p0 = (size_t)row * DM + col;
                size_t p1 = (size_t)(row + 8) * DM + col;
                float v0 = acc[mt][nt][0], v1 = acc[mt][nt][1];
                float v2 = acc[mt][nt][2], v3 = acc[mt][nt][3];
                __half2 h01 = __floats2half2_rn(v0, v1);
                __half2 h23 = __floats2half2_rn(v2, v3);
                *(__half2*)(Qh + p0) = h01;
                *(__half2*)(Qh + p1) = h23;
                *(__half2*)(Ql + p0) = __floats2half2_rn(
                    v0 - __half2float(h01.x), v1 - __half2float(h01.y));
                *(__half2*)(Ql + p1) = __floats2half2_rn(
                    v2 - __half2float(h23.x), v3 - __half2float(h23.y));
            }
    } else {
        const int n = (blockIdx.x << 1) + wn;
        float rwv[8][2];
        if (mat == 1) {
#pragma unroll
            for (int nt = 0; nt < 8; ++nt) {
                float2 t = *(const float2*)(rwb + n * DH + nt * 8 + 2 * (lane & 3));
                rwv[nt][0] = t.x; rwv[nt][1] = t.y;
            }
        }
#pragma unroll
        for (int mt = 0; mt < 2; ++mt) {
#pragma unroll
            for (int half = 0; half < 2; ++half) {
                const int row = r0 + wm * 32 + mt * 16 + (lane >> 2) + half * 8;
                const int b = row >> 10, j = row & 1023;
                const bool has = (j + 1) < QL;
                float dot = 0.f;
                float vals[8][2];
#pragma unroll
                for (int nt = 0; nt < 8; ++nt) {
                    float v0 = acc[mt][nt][half * 2 + 0];
                    float v1 = acc[mt][nt][half * 2 + 1];
                    if (mat == 1) {
                        dot += rwv[nt][0] * v0 + rwv[nt][1] * v1;
                        const int d = nt * 8 + 2 * (lane & 3);
                        float2 re = has
                            ? *(const float2*)(remb + ((size_t)(j + 1) * NHEAD + n) * DH + d)
                            : make_float2(0.f, 0.f);
                        v0 += re.x; v1 += re.y;
                    }
                    vals[nt][0] = v0; vals[nt][1] = v1;
                }
                const size_t base =
                    ((size_t)(b * NHEAD + n) * QL + j) * DH + 2 * (lane & 3);
                if (mat == 1) {
#pragma unroll
                    for (int nt = 0; nt < 8; ++nt) {
                        __half2 h2 = __floats2half2_rn(vals[nt][0], vals[nt][1]);
                        *(__half2*)(Cbh + base + nt * 8) = h2;
                        *(__half2*)(Cbl + base + nt * 8) = __floats2half2_rn(
                            vals[nt][0] - __half2float(h2.x),
                            vals[nt][1] - __half2float(h2.y));
                    }
                    dot += __shfl_xor_sync(0xffffffffu, dot, 1);
                    dot += __shfl_xor_sync(0xffffffffu, dot, 2);
                    if ((lane & 3) == 0)
                        tsg[(size_t)(b * NHEAD + n) * QL + j] =
                            dot + (has ? rbias[(size_t)(j + 1) * NHEAD + n] : 0.f);
                } else {
#pragma unroll
                    for (int nt = 0; nt < 8; ++nt)
                        *(__half2*)(Vbh + base + nt * 8) =
                            __floats2half2_rn(vals[nt][0], vals[nt][1]);
                }
            }
        }
    }
}

// ===========================================================================
// Wo GEMM: CTA 128x128, 256 threads, 2 CTAs/SM, single fp16 pass, BK=64.
// Stage: A 16KB | B 16KB = 32KB (128B rows, SWOFF swizzle). 3 stages = 96KB.
// 16 chunks of K=64 (4 k16 steps each).
// ===========================================================================
#define NCW 16
#define STGW 32768
#define SMEM_WO (3 * STGW)

__global__ __launch_bounds__(256, 2) void gemm_wo(
    const __half* __restrict__ Ah, const __half* __restrict__ Bh,
    float* __restrict__ F0)
{
    extern __shared__ char smem[];
    const uint32_t sb = smem_to_u32(smem);
    const int tid = threadIdx.x;
    const int wid = tid >> 5, lane = tid & 31;
    const int wm = wid >> 1, wn = wid & 1;
    const int c0 = blockIdx.x * 128;
    const int r0 = blockIdx.y * 128;

    const char* AgH = (const char*)(Ah + (size_t)r0 * GK);
    const char* BgH = (const char*)(Bh + (size_t)c0 * GK);

    // per stage: A 128 rows x 8 chunks = 1024 chunks; same for B; 8/thread total
    auto load_stage = [&](int st, int ck) {
        const uint32_t s0 = sb + st * STGW;
        const size_t gofs = (size_t)ck * 128;   // 64 fp16 = 128B along K
#pragma unroll
        for (int h = 0; h < 4; ++h) {
            int idx = h * 256 + tid;
            int row = idx >> 3, ch = idx & 7;
            uint32_t o = SWOFF(row, ch);
            size_t g = (size_t)row * 2048 + gofs + ch * 16;
            CP_ASYNC16(s0 + o, AgH + g);
            CP_ASYNC16(s0 + 16384 + o, BgH + g);
        }
    };

    load_stage(0, 0); CP_ASYNC_COMMIT();
    load_stage(1, 1); CP_ASYNC_COMMIT();

    float acc[2][8][4];
#pragma unroll
    for (int mt = 0; mt < 2; ++mt)
#pragma unroll
        for (int nt = 0; nt < 8; ++nt)
#pragma unroll
            for (int r = 0; r < 4; ++r) acc[mt][nt][r] = 0.f;

    const int sub = lane >> 3, l7 = lane & 7;

    for (int i = 0; i < NCW; ++i) {
        CP_ASYNC_WAIT1();
        __syncthreads();
        if (i + 2 < NCW) load_stage((i + 2) % 3, i + 2);
        CP_ASYNC_COMMIT();

        const uint32_t sA = sb + (i % 3) * STGW;
        const uint32_t sB = sA + 16384;

#pragma unroll
        for (int ks = 0; ks < 4; ++ks) {
            uint32_t ah[2][4];
#pragma unroll
            for (int mt = 0; mt < 2; ++mt) {
                int row = wm * 32 + mt * 16 + ((sub & 1) << 3) + l7;
                int ch = 2 * ks + (sub >> 1);
                uint32_t off = SWOFF(row, ch);
                LDSM4(ah[mt][0], ah[mt][1], ah[mt][2], ah[mt][3], sA + off);
            }
#pragma unroll
            for (int ntp = 0; ntp < 4; ++ntp) {
                int row = wn * 64 + ntp * 16 + ((sub >> 1) << 3) + l7;
                int ch = 2 * ks + (sub & 1);
                uint32_t off = SWOFF(row, ch);
                uint32_t bh2[2][2];
                LDSM4(bh2[0][0], bh2[0][1], bh2[1][0], bh2[1][1], sB + off);
#pragma unroll
                for (int h = 0; h < 2; ++h) {
                    const int nt = 2 * ntp + h;
#pragma unroll
                    for (int mt = 0; mt < 2; ++mt)
                        MMA_F16(acc[mt][nt], ah[mt], bh2[h]);
                }
            }
        }
    }

#pragma unroll
    for (int mt = 0; mt < 2; ++mt)
#pragma unroll
        for (int nt = 0; nt < 8; ++nt) {
            int row = r0 + wm * 32 + mt * 16 + (lane >> 2);
            int col = c0 + wn * 64 + nt * 8 + 2 * (lane & 3);
            *(float2*)(F0 + (size_t)row * DM + col) =
                make_float2(acc[mt][nt][0], acc[mt][nt][1]);
            *(float2*)(F0 + (size_t)(row + 8) * DM + col) =
                make_float2(acc[mt][nt][2], acc[mt][nt][3]);
        }
}

// ===========================================================================
// MMA flash attention: 64-query tile, 128 threads, 3 CTAs/SM (R12/R14 exact).
// ===========================================================================
#define ATT_STG 24832
#define ATT_SMEM (2 * ATT_STG)

__global__ __launch_bounds__(128, 3) void attn_mma(
    const __half* __restrict__ qbh, const __half* __restrict__ qbl,
    const __half* __restrict__ cbh, const __half* __restrict__ cbl,
    const __half* __restrict__ vbh,
    const float* __restrict__ tsg,
    __half* __restrict__ avh)
{
    extern __shared__ char sm[];
    const uint32_t sb = smem_to_u32(sm);

    const int tid = threadIdx.x;
    const int wid = tid >> 5, lane = tid & 31;
    const int sub = lane >> 3, l7 = lane & 7;
    const int i0 = blockIdx.x * 64, n = blockIdx.y, b = blockIdx.z;

    const size_t kvb = ((size_t)(b * NHEAD + n) * QL) * DH * 2;
    const char* chg = (const char*)cbh + kvb;
    const char* clg = (const char*)cbl + kvb;
    const char* vhg = (const char*)vbh + kvb;
    const char* tg = (const char*)(tsg + (size_t)(b * NHEAD + n) * QL);

    {
        const char* qhg = (const char*)qbh + ((size_t)(b * QL + i0) * DM + n * DH) * 2;
        const char* qlg = (const char*)qbl + ((size_t)(b * QL + i0) * DM + n * DH) * 2;
#pragma unroll
        for (int r = 0; r < 4; ++r) {
            int id = r * 128 + tid;
            int row = id >> 3, ch = id & 7;
            uint32_t o = SWOFF(row, ch);
            CP_ASYNC16(sb + o, qhg + (size_t)row * 2048 + ch * 16);
            CP_ASYNC16(sb + 8192 + o, qlg + (size_t)row * 2048 + ch * 16);
        }
        CP_ASYNC_COMMIT();
    }

    auto load_stage = [&](int s, int jt) {
        const uint32_t st = sb + s * ATT_STG;
        const size_t go = (size_t)jt * 64 * 128;
#pragma unroll
        for (int r = 0; r < 4; ++r) {
            int id = r * 128 + tid;
            int row = id >> 3, ch = id & 7;
            uint32_t o = SWOFF(row, ch);
            size_t g = go + (size_t)row * 128 + ch * 16;
            CP_ASYNC16(st + o, chg + g);
            CP_ASYNC16(st + 8192 + o, clg + g);
            CP_ASYNC16(st + 16384 + o, vhg + g);
        }
        if (tid < 16) CP_ASYNC16(st + 24576 + tid * 16, tg + (size_t)jt * 256 + tid * 16);
    };

    load_stage(1, 0); CP_ASYNC_COMMIT();

    CP_ASYNC_WAIT1();
    __syncthreads();

    uint32_t qhf[4][4], qlf[4][4];
#pragma unroll
    for (int kc = 0; kc < 4; ++kc) {
        int row = wid * 16 + ((sub & 1) << 3) + l7;
        int ch = 2 * kc + (sub >> 1);
        uint32_t o = SWOFF(row, ch);
        LDSM4(qhf[kc][0], qhf[kc][1], qhf[kc][2], qhf[kc][3], sb + o);
        LDSM4(qlf[kc][0], qlf[kc][1], qlf[kc][2], qlf[kc][3], sb + 8192 + o);
    }
    __syncthreads();

    load_stage(0, 1); CP_ASYNC_COMMIT();

    float o_[8][4];
    float m0 = -1e30f, m1 = -1e30f, l0 = 0.f, l1 = 0.f;
#pragma unroll
    for (int t = 0; t < 8; ++t)
#pragma unroll
        for (int r = 0; r < 4; ++r) o_[t][r] = 0.f;

    for (int jt = 0; jt < 16; ++jt) {
        CP_ASYNC_WAIT1();
        __syncthreads();

        const int s = (jt + 1) & 1;
        const uint32_t st = sb + s * ATT_STG;
        const float* tsp = (const float*)(sm + s * ATT_STG + 24576);

        float sc[8][4];
#pragma unroll
        for (int t = 0; t < 8; ++t)
#pragma unroll
            for (int r = 0; r < 4; ++r) sc[t][r] = 0.f;

#pragma unroll
        for (int kc = 0; kc < 4; ++kc) {
#pragma unroll
            for (int p = 0; p < 4; ++p) {
                int row = p * 16 + ((sub >> 1) << 3) + l7;
                int ch = 2 * kc + (sub & 1);
                uint32_t o = SWOFF(row, ch);
                uint32_t bh[2][2], bl[2][2];
                LDSM4(bh[0][0], bh[0][1], bh[1][0], bh[1][1], st + o);
                LDSM4(bl[0][0], bl[0][1], bl[1][0], bl[1][1], st + 8192 + o);
#pragma unroll
                for (int h = 0; h < 2; ++h) {
                    MMA_F16(sc[2 * p + h], qhf[kc], bh[h]);
                    MMA_F16(sc[2 * p + h], qhf[kc], bl[h]);
                    MMA_F16(sc[2 * p + h], qlf[kc], bh[h]);
                }
            }
        }

#pragma unroll
        for (int t = 0; t < 8; ++t) {
            float2 tv = *(const float2*)(tsp + t * 8 + (lane & 3) * 2);
            sc[t][0] = (sc[t][0] + tv.x) * 0.125f;
            sc[t][1] = (sc[t][1] + tv.y) * 0.125f;
            sc[t][2] = (sc[t][2] + tv.x) * 0.125f;
            sc[t][3] = (sc[t][3] + tv.y) * 0.125f;
        }

        float mx0 = -1e30f, mx1 = -1e30f;
#pragma unroll
        for (int t = 0; t < 8; ++t) {
            mx0 = fmaxf(mx0, fmaxf(sc[t][0], sc[t][1]));
            mx1 = fmaxf(mx1, fmaxf(sc[t][2], sc[t][3]));
        }
        mx0 = fmaxf(mx0, __shfl_xor_sync(0xffffffffu, mx0, 1));
        mx0 = fmaxf(mx0, __shfl_xor_sync(0xffffffffu, mx0, 2));
        mx1 = fmaxf(mx1, __shfl_xor_sync(0xffffffffu, mx1, 1));
        mx1 = fmaxf(mx1, __shfl_xor_sync(0xffffffffu, mx1, 2));
        const float nm0 = fmaxf(m0, mx0), nm1 = fmaxf(m1, mx1);
        const float a0 = __expf(m0 - nm0), a1 = __expf(m1 - nm1);
        m0 = nm0; m1 = nm1;

        float sum0 = 0.f, sum1 = 0.f;
#pragma unroll
        for (int t = 0; t < 8; ++t) {
            sc[t][0] = __expf(sc[t][0] - nm0);
            sc[t][1] = __expf(sc[t][1] - nm0);
            sc[t][2] = __expf(sc[t][2] - nm1);
            sc[t][3] = __expf(sc[t][3] - nm1);
            sum0 += sc[t][0] + sc[t][1];
            sum1 += sc[t][2] + sc[t][3];
        }
        sum0 += __shfl_xor_sync(0xffffffffu, sum0, 1);
        sum0 += __shfl_xor_sync(0xffffffffu, sum0, 2);
        sum1 += __shfl_xor_sync(0xffffffffu, sum1, 1);
        sum1 += __shfl_xor_sync(0xffffffffu, sum1, 2);
        l0 = l0 * a0 + sum0;
        l1 = l1 * a1 + sum1;
#pragma unroll
        for (int t = 0; t < 8; ++t) {
            o_[t][0] *= a0; o_[t][1] *= a0;
            o_[t][2] *= a1; o_[t][3] *= a1;
        }

#pragma unroll
        for (int kc = 0; kc < 4; ++kc) {
            uint32_t ah[4];
#pragma unroll
            for (int h = 0; h < 2; ++h) {
                const int t = 2 * kc + h;
                __half2 p01 = __floats2half2_rn(sc[t][0], sc[t][1]);
                __half2 p23 = __floats2half2_rn(sc[t][2], sc[t][3]);
                ah[2 * h + 0] = *(uint32_t*)&p01;
                ah[2 * h + 1] = *(uint32_t*)&p23;
            }
#pragma unroll
            for (int g = 0; g < 4; ++g) {
                int row = 16 * kc + ((sub & 1) << 3) + l7;
                int ch = 2 * g + (sub >> 1);
                uint32_t o = SWOFF(row, ch);
                uint32_t vh[2][2];
                LDSM4T(vh[0][0], vh[0][1], vh[1][0], vh[1][1], st + 16384 + o);
#pragma unroll
                for (int h = 0; h < 2; ++h)
                    MMA_F16(o_[2 * g + h], ah, vh[h]);
            }
        }

        __syncthreads();
        if (jt + 2 < 16) load_stage(s, jt + 2);
        CP_ASYNC_COMMIT();
    }

    const float inv0 = 1.f / l0, inv1 = 1.f / l1;
    const int row0 = i0 + wid * 16 + (lane >> 2);
#pragma unroll
    for (int t = 0; t < 8; ++t) {
        const int col = n * DH + t * 8 + (lane & 3) * 2;
        float v0 = o_[t][0] * inv0, v1 = o_[t][1] * inv0;
        float v2 = o_[t][2] * inv1, v3 = o_[t][3] * inv1;
        size_t p0 = (size_t)(b * QL + row0) * DM + col;
        size_t p1 = (size_t)(b * QL + row0 + 8) * DM + col;
        *(__half2*)(avh + p0) = __floats2half2_rn(v0, v1);
        *(__half2*)(avh + p1) = __floats2half2_rn(v2, v3);
    }
}

// ===========================================================================
// Residual + LayerNorm
// ===========================================================================
__global__ __launch_bounds__(256) void ln_kernel(
    const float* __restrict__ w, const float* __restrict__ ao,
    const float* __restrict__ gamma, const float* __restrict__ beta,
    float* __restrict__ out)
{
    __shared__ float ssum[8], ssq[8];
    const int row = blockIdx.x;
    const int tid = threadIdx.x;
    const size_t base = (size_t)row * DM + tid * 4;

    float4 x = *(const float4*)(w + base);
    float4 a = *(const float4*)(ao + base);
    x.x += a.x; x.y += a.y; x.z += a.z; x.w += a.w;

    float sum = x.x + x.y + x.z + x.w;
    float sq = x.x * x.x + x.y * x.y + x.z * x.z + x.w * x.w;
#pragma unroll
    for (int off = 16; off; off >>= 1) {
        sum += __shfl_xor_sync(0xffffffffu, sum, off);
        sq += __shfl_xor_sync(0xffffffffu, sq, off);
    }
    const int wid = tid >> 5;
    if ((tid & 31) == 0) { ssum[wid] = sum; ssq[wid] = sq; }
    __syncthreads();
    sum = 0.f; sq = 0.f;
#pragma unroll
    for (int i = 0; i < 8; ++i) { sum += ssum[i]; sq += ssq[i]; }

    const float mu = sum * (1.f / DM);
    const float var = sq * (1.f / DM) - mu * mu;
    const float inv = rsqrtf(var + 1e-5f);

    float4 g = *(const float4*)(gamma + (size_t)tid * 4);
    float4 be = *(const float4*)(beta + (size_t)tid * 4);
    float4 r;
    r.x = (x.x - mu) * inv * g.x + be.x;
    r.y = (x.y - mu) * inv * g.y + be.y;
    r.z = (x.z - mu) * inv * g.z + be.z;
    r.w = (x.w - mu) * inv * g.w + be.w;
    *(float4*)(out + base) = r;
}

// ===========================================================================
extern "C" void kernel_launch(void* const* d_in, const int* in_sizes, int n_in,
                              void* d_out, int out_size)
{
    (void)in_sizes; (void)n_in; (void)out_size;
    const float* w      = (const float*)d_in[0];
    const float* r_emb  = (const float*)d_in[1];
    const float* r_w_b  = (const float*)d_in[2];
    const float* r_bias = (const float*)d_in[3];
    const float* Wq     = (const float*)d_in[4];
    const float* Wk     = (const float*)d_in[5];
    const float* Wv     = (const float*)d_in[6];
    const float* Wo     = (const float*)d_in[7];
    const float* gamma  = (const float*)d_in[8];
    const float* beta   = (const float*)d_in[9];
    float* out = (float*)d_out;

    float *ao, *tsg;
    __half *wh, *wl, *avh, *bh, *bl;
    __half *qbh, *qbl, *cbh, *cbl, *vbh;
    cudaGetSymbolAddress((void**)&ao, g_ao);
    cudaGetSymbolAddress((void**)&wh, g_wh);
    cudaGetSymbolAddress((void**)&wl, g_wl);
    cudaGetSymbolAddress((void**)&avh, g_avh);
    cudaGetSymbolAddress((void**)&bh, g_bh);
    cudaGetSymbolAddress((void**)&bl, g_bl);
    cudaGetSymbolAddress((void**)&qbh, g_qbh);
    cudaGetSymbolAddress((void**)&qbl, g_qbl);
    cudaGetSymbolAddress((void**)&cbh, g_cbh);
    cudaGetSymbolAddress((void**)&cbl, g_cbl);
    cudaGetSymbolAddress((void**)&vbh, g_vbh);
    cudaGetSymbolAddress((void**)&tsg, g_ts);

    prep_all<<<dim3(32, 32, 8), 256>>>(w, Wq, Wk, Wv, Wo, wh, wl, bh, bl);

    cudaFuncSetAttribute(gemm_qkv,
                         cudaFuncAttributeMaxDynamicSharedMemorySize, SMEM_G64);
    gemm_qkv<<<dim3(8, 192), 128, SMEM_G64>>>(
        wh, wl, bh, bl, r_emb, r_w_b, r_bias,
        qbh, qbl, cbh, cbl, vbh, tsg);

    cudaFuncSetAttribute(attn_mma,
                         cudaFuncAttributeMaxDynamicSharedMemorySize, ATT_SMEM);
    attn_mma<<<dim3(QL / 64, NHEAD, BB), 128, ATT_SMEM>>>(
        qbh, qbl, cbh, cbl, vbh, tsg, avh);

    cudaFuncSetAttribute(gemm_wo,
                         cudaFuncAttributeMaxDynamicSharedMemorySize, SMEM_WO);
    gemm_wo<<<dim3(8, 32), 256, SMEM_WO>>>(
        avh, bh + 3 * (size_t)DM * DM, ao);

    ln_kernel<<<MTOT, 256>>>(w, ao, gamma, beta, out);
}

// round 16
// speedup vs baseline: 1.0810x; 1.0029x over previous
#include <cuda_runtime.h>
#include <cuda_fp16.h>
#include <cstdint>

#define BB 4
#define QL 1024
#define DM 1024
#define NHEAD 16
#define DH 64
#define MTOT (BB * QL)  // 4096

// scale folded into log2 domain: 0.125 * log2(e)
#define SC_L2 0.18033688f

// fp32 scratch
__device__ float g_ao[(size_t)MTOT * DM];
// fp16 split operands
__device__ __half g_wh[(size_t)MTOT * DM];
__device__ __half g_wl[(size_t)MTOT * DM];
__device__ __half g_avh[(size_t)MTOT * DM];
__device__ __half g_bh[(size_t)4 * DM * DM];
__device__ __half g_bl[(size_t)4 * DM * DM];
// attention operands
__device__ __half g_qbh[(size_t)MTOT * DM];
__device__ __half g_qbl[(size_t)MTOT * DM];
__device__ __half g_cbh[(size_t)BB * NHEAD * QL * DH];
__device__ __half g_cbl[(size_t)BB * NHEAD * QL * DH];
__device__ __half g_vbh[(size_t)BB * NHEAD * QL * DH];
__device__ float g_ts[(size_t)BB * NHEAD * QL];

// ===========================================================================
// PTX helpers (portable sm_80/90-class only)
// ===========================================================================
__device__ __forceinline__ uint32_t smem_to_u32(const void* p) {
    uint32_t a;
    asm("{ .reg .u64 t; cvta.to.shared.u64 t, %1; cvt.u32.u64 %0, t; }"
        : "=r"(a) : "l"(p));
    return a;
}
__device__ __forceinline__ float ex2f(float x) {
    float r;
    asm("ex2.approx.f32 %0, %1;" : "=f"(r) : "f"(x));
    return r;
}
#define CP_ASYNC16(s, g) \
    asm volatile("cp.async.cg.shared.global [%0], [%1], 16;" :: "r"(s), "l"(g) : "memory")
#define CP_ASYNC_COMMIT() asm volatile("cp.async.commit_group;" ::: "memory")
#define CP_ASYNC_WAIT1() asm volatile("cp.async.wait_group 1;" ::: "memory")

#define LDSM4(r0, r1, r2, r3, addr)                                            \
    asm volatile("ldmatrix.sync.aligned.m8n8.x4.shared.b16 {%0,%1,%2,%3}, [%4];" \
                 : "=r"(r0), "=r"(r1), "=r"(r2), "=r"(r3) : "r"(addr))
#define LDSM4T(r0, r1, r2, r3, addr)                                           \
    asm volatile("ldmatrix.sync.aligned.m8n8.x4.trans.shared.b16 {%0,%1,%2,%3}, [%4];" \
                 : "=r"(r0), "=r"(r1), "=r"(r2), "=r"(r3) : "r"(addr))

#define MMA_F16(d, a, b)                                                       \
    asm volatile("mma.sync.aligned.m16n8k16.row.col.f32.f16.f16.f32 "          \
                 "{%0,%1,%2,%3}, {%4,%5,%6,%7}, {%8,%9}, {%0,%1,%2,%3};"       \
                 : "+f"((d)[0]), "+f"((d)[1]), "+f"((d)[2]), "+f"((d)[3])      \
                 : "r"((a)[0]), "r"((a)[1]), "r"((a)[2]), "r"((a)[3]),         \
                   "r"((b)[0]), "r"((b)[1]))

// 64B rows (32 fp16), 4x16B chunks
#define SW64(row, ch) ((row) * 64 + (((ch) ^ (((row) >> 1) & 3)) << 4))
// 128B rows (64 fp16), 8x16B chunks
#define SWOFF(row, ch) ((row) * 128 + (((ch) ^ ((row) & 7)) << 4))

// ===========================================================================
// prep_all: z<4 -> weight transpose+split; z>=4 -> activation split (fp16)
// ===========================================================================
__global__ __launch_bounds__(256) void prep_all(
    const float* __restrict__ w,
    const float* __restrict__ s0, const float* __restrict__ s1,
    const float* __restrict__ s2, const float* __restrict__ s3,
    __half* __restrict__ wh, __half* __restrict__ wl,
    __half* __restrict__ bh, __half* __restrict__ bl)
{
    const int z = blockIdx.z;
    if (z >= 4) {
        int i = (((z - 4) * 32 + blockIdx.y) * 32 + blockIdx.x) * 256 + threadIdx.x;
        float4 a = ((const float4*)w)[i];
        __half h0 = __float2half_rn(a.x), h1 = __float2half_rn(a.y);
        __half h2 = __float2half_rn(a.z), h3 = __float2half_rn(a.w);
        ((__half2*)wh)[i * 2 + 0] = __halves2half2(h0, h1);
        ((__half2*)wh)[i * 2 + 1] = __halves2half2(h2, h3);
        ((__half2*)wl)[i * 2 + 0] = __halves2half2(
            __float2half_rn(a.x - __half2float(h0)),
            __float2half_rn(a.y - __half2float(h1)));
        ((__half2*)wl)[i * 2 + 1] = __halves2half2(
            __float2half_rn(a.z - __half2float(h2)),
            __float2half_rn(a.w - __half2float(h3)));
        return;
    }
    __shared__ float t[32][33];
    const float* S = z == 0 ? s0 : z == 1 ? s1 : z == 2 ? s2 : s3;
    __half* H = bh + (size_t)z * DM * DM;
    __half* L = bl + (size_t)z * DM * DM;
    const int x = blockIdx.x * 32, y = blockIdx.y * 32;
    const int tx = threadIdx.x & 31, ty = threadIdx.x >> 5;
#pragma unroll
    for (int i = 0; i < 32; i += 8)
        t[ty + i][tx] = S[(size_t)(y + ty + i) * DM + x + tx];
    __syncthreads();
    const int c = (threadIdx.x & 15) * 2;
    const int rb = threadIdx.x >> 4;
#pragma unroll
    for (int i = 0; i < 32; i += 16) {
        const int r = rb + i;
        float a0 = t[c][r], a1 = t[c + 1][r];
        __half h0 = __float2half_rn(a0), h1 = __float2half_rn(a1);
        size_t idx = (size_t)(x + r) * DM + y + c;
        *(__half2*)(H + idx) = __halves2half2(h0, h1);
        *(__half2*)(L + idx) = __halves2half2(
            __float2half_rn(a0 - __half2float(h0)),
            __float2half_rn(a1 - __half2float(h1)));
    }
}

// ===========================================================================
// QKV GEMM: CTA 64x128, 128 threads, 3 CTAs/SM, grid (8,192) mat-major.
// mat 0 (Q), 1 (K->C + ts*SC_L2): fp16x3. mat 2 (V): fp16 single pass.
// ===========================================================================
#define GK 1024
#define NCH 32
#define STG3 24576
#define SMEM_G64 (3 * STG3)

__global__ __launch_bounds__(128, 3) void gemm_qkv(
    const __half* __restrict__ Ah, const __half* __restrict__ Al,
    const __half* __restrict__ Bh, const __half* __restrict__ Bl,
    const float* __restrict__ remb, const float* __restrict__ rwb,
    const float* __restrict__ rbias,
    __half* __restrict__ Qh, __half* __restrict__ Ql,
    __half* __restrict__ Cbh, __half* __restrict__ Cbl,
    __half* __restrict__ Vbh,
    float* __restrict__ tsg)
{
    extern __shared__ char smem[];
    const uint32_t sb = smem_to_u32(smem);
    const int tid = threadIdx.x;
    const int wid = tid >> 5, lane = tid & 31;
    const int wm = wid >> 1, wn = wid & 1;
    const int mat = blockIdx.y >> 6;
    const int c0 = blockIdx.x * 128;
    const int r0 = (blockIdx.y & 63) * 64;
    const bool third = (mat != 2);

    const char* AgH = (const char*)(Ah + (size_t)r0 * GK);
    const char* AgL = (const char*)(Al + (size_t)r0 * GK);
    const char* BgH = (const char*)(Bh + (size_t)mat * DM * DM + (size_t)c0 * GK);
    const char* BgL = (const char*)(Bl + (size_t)mat * DM * DM + (size_t)c0 * GK);

    auto load_stage = [&](int st, int ck) {
        const uint32_t s0 = sb + st * STG3;
        const size_t gofs = (size_t)ck * 64;
#pragma unroll
        for (int h = 0; h < 2; ++h) {
            int idx = h * 128 + tid;
            int row = idx >> 2, ch = idx & 3;
            uint32_t o = SW64(row, ch);
            size_t g = (size_t)row * 2048 + gofs + ch * 16;
            CP_ASYNC16(s0 + o, AgH + g);
            if (third) CP_ASYNC16(s0 + 4096 + o, AgL + g);
        }
#pragma unroll
        for (int h = 0; h < 4; ++h) {
            int idx = h * 128 + tid;
            int row = idx >> 2, ch = idx & 3;
            uint32_t o = SW64(row, ch);
            size_t g = (size_t)row * 2048 + gofs + ch * 16;
            CP_ASYNC16(s0 + 8192 + o, BgH + g);
            if (third) CP_ASYNC16(s0 + 16384 + o, BgL + g);
        }
    };

    load_stage(0, 0); CP_ASYNC_COMMIT();
    load_stage(1, 1); CP_ASYNC_COMMIT();

    float acc[2][8][4];
#pragma unroll
    for (int mt = 0; mt < 2; ++mt)
#pragma unroll
        for (int nt = 0; nt < 8; ++nt)
#pragma unroll
            for (int r = 0; r < 4; ++r) acc[mt][nt][r] = 0.f;

    const int sub = lane >> 3, l7 = lane & 7;

    for (int i = 0; i < NCH; ++i) {
        CP_ASYNC_WAIT1();
        __syncthreads();
        if (i + 2 < NCH) load_stage((i + 2) % 3, i + 2);
        CP_ASYNC_COMMIT();

        const uint32_t sA = sb + (i % 3) * STG3;
        const uint32_t sB = sA + 8192;

#pragma unroll
        for (int ks = 0; ks < 2; ++ks) {
            uint32_t ah[2][4], al[2][4], bh2[4][2][2], bl2[4][2][2];
#pragma unroll
            for (int mt = 0; mt < 2; ++mt) {
                int row = wm * 32 + mt * 16 + ((sub & 1) << 3) + l7;
                int ch = 2 * ks + (sub >> 1);
                uint32_t off = SW64(row, ch);
                LDSM4(ah[mt][0], ah[mt][1], ah[mt][2], ah[mt][3], sA + off);
                if (third)
                    LDSM4(al[mt][0], al[mt][1], al[mt][2], al[mt][3],
                          sA + 4096 + off);
            }
#pragma unroll
            for (int ntp = 0; ntp < 4; ++ntp) {
                int row = wn * 64 + ntp * 16 + ((sub >> 1) << 3) + l7;
                int ch = 2 * ks + (sub & 1);
                uint32_t off = SW64(row, ch);
                LDSM4(bh2[ntp][0][0], bh2[ntp][0][1], bh2[ntp][1][0],
                      bh2[ntp][1][1], sB + off);
                if (third)
                    LDSM4(bl2[ntp][0][0], bl2[ntp][0][1], bl2[ntp][1][0],
                          bl2[ntp][1][1], sB + 8192 + off);
            }
#pragma unroll
            for (int ntp = 0; ntp < 4; ++ntp)
#pragma unroll
                for (int h = 0; h < 2; ++h)
#pragma unroll
                    for (int mt = 0; mt < 2; ++mt)
                        MMA_F16(acc[mt][2 * ntp + h], ah[mt], bh2[ntp][h]);
            if (third) {
#pragma unroll
                for (int ntp = 0; ntp < 4; ++ntp)
#pragma unroll
                    for (int h = 0; h < 2; ++h)
#pragma unroll
                        for (int mt = 0; mt < 2; ++mt) {
                            MMA_F16(acc[mt][2 * ntp + h], ah[mt], bl2[ntp][h]);
                            MMA_F16(acc[mt][2 * ntp + h], al[mt], bh2[ntp][h]);
                        }
            }
        }
    }

    if (mat == 0) {
#pragma unroll
        for (int mt = 0; mt < 2; ++mt)
#pragma unroll
            for (int nt = 0; nt < 8; ++nt) {
                int row = r0 + wm * 32 + mt * 16 + (lane >> 2);
                int col = c0 + wn * 64 + nt * 8 + 2 * (lane & 3);
                size_t p0 = (size_t)row * DM + col;
                size_t p1 = (size_t)(row + 8) * DM + col;
                float v0 = acc[mt][nt][0], v1 = acc[mt][nt][1];
                float v2 = acc[mt][nt][2], v3 = acc[mt][nt][3];
                __half2 h01 = __floats2half2_rn(v0, v1);
                __half2 h23 = __floats2half2_rn(v2, v3);
                *(__half2*)(Qh + p0) = h01;
                *(__half2*)(Qh + p1) = h23;
                *(__half2*)(Ql + p0) = __floats2half2_rn(
                    v0 - __half2float(h01.x), v1 - __half2float(h01.y));
                *(__half2*)(Ql + p1) = __floats2half2_rn(
                    v2 - __half2float(h23.x), v3 - __half2float(h23.y));
            }
    } else {
        const int n = (blockIdx.x << 1) + wn;
        float rwv[8][2];
        if (mat == 1) {
#pragma unroll
            for (int nt = 0; nt < 8; ++nt) {
                float2 t = *(const float2*)(rwb + n * DH + nt * 8 + 2 * (lane & 3));
                rwv[nt][0] = t.x; rwv[nt][1] = t.y;
            }
        }
#pragma unroll
        for (int mt = 0; mt < 2; ++mt) {
#pragma unroll
            for (int half = 0; half < 2; ++half) {
                const int row = r0 + wm * 32 + mt * 16 + (lane >> 2) + half * 8;
                const int b = row >> 10, j = row & 1023;
                const bool has = (j + 1) < QL;
                float dot = 0.f;
                float vals[8][2];
#pragma unroll
                for (int nt = 0; nt < 8; ++nt) {
                    float v0 = acc[mt][nt][half * 2 + 0];
                    float v1 = acc[mt][nt][half * 2 + 1];
                    if (mat == 1) {
                        dot += rwv[nt][0] * v0 + rwv[nt][1] * v1;
                        const int d = nt * 8 + 2 * (lane & 3);
                        float2 re = has
                            ? *(const float2*)(remb + ((size_t)(j + 1) * NHEAD + n) * DH + d)
                            : make_float2(0.f, 0.f);
                        v0 += re.x; v1 += re.y;
                    }
                    vals[nt][0] = v0; vals[nt][1] = v1;
                }
                const size_t base =
                    ((size_t)(b * NHEAD + n) * QL + j) * DH + 2 * (lane & 3);
                if (mat == 1) {
#pragma unroll
                    for (int nt = 0; nt < 8; ++nt) {
                        __half2 h2 = __floats2half2_rn(vals[nt][0], vals[nt][1]);
                        *(__half2*)(Cbh + base + nt * 8) = h2;
                        *(__half2*)(Cbl + base + nt * 8) = __floats2half2_rn(
                            vals[nt][0] - __half2float(h2.x),
                            vals[nt][1] - __half2float(h2.y));
                    }
                    dot += __shfl_xor_sync(0xffffffffu, dot, 1);
                    dot += __shfl_xor_sync(0xffffffffu, dot, 2);
                    if ((lane & 3) == 0)
                        tsg[(size_t)(b * NHEAD + n) * QL + j] =
                            (dot + (has ? rbias[(size_t)(j + 1) * NHEAD + n] : 0.f))
                            * SC_L2;
                } else {
#pragma unroll
                    for (int nt = 0; nt < 8; ++nt)
                        *(__half2*)(Vbh + base + nt * 8) =
                            __floats2half2_rn(vals[nt][0], vals[nt][1]);
                }
            }
        }
    }
}

// ===========================================================================
// Wo GEMM: CTA 128x128, 256 threads, 2 CTAs/SM, single fp16 pass, BK=64 (R15).
// ===========================================================================
#define NCW 16
#define STGW 32768
#define SMEM_WO (3 * STGW)

__global__ __launch_bounds__(256, 2) void gemm_wo(
    const __half* __restrict__ Ah, const __half* __restrict__ Bh,
    float* __restrict__ F0)
{
    extern __shared__ char smem[];
    const uint32_t sb = smem_to_u32(smem);
    const int tid = threadIdx.x;
    const int wid = tid >> 5, lane = tid & 31;
    const int wm = wid >> 1, wn = wid & 1;
    const int c0 = blockIdx.x * 128;
    const int r0 = blockIdx.y * 128;

    const char* AgH = (const char*)(Ah + (size_t)r0 * GK);
    const char* BgH = (const char*)(Bh + (size_t)c0 * GK);

    auto load_stage = [&](int st, int ck) {
        const uint32_t s0 = sb + st * STGW;
        const size_t gofs = (size_t)ck * 128;
#pragma unroll
        for (int h = 0; h < 4; ++h) {
            int idx = h * 256 + tid;
            int row = idx >> 3, ch = idx & 7;
            uint32_t o = SWOFF(row, ch);
            size_t g = (size_t)row * 2048 + gofs + ch * 16;
            CP_ASYNC16(s0 + o, AgH + g);
            CP_ASYNC16(s0 + 16384 + o, BgH + g);
        }
    };

    load_stage(0, 0); CP_ASYNC_COMMIT();
    load_stage(1, 1); CP_ASYNC_COMMIT();

    float acc[2][8][4];
#pragma unroll
    for (int mt = 0; mt < 2; ++mt)
#pragma unroll
        for (int nt = 0; nt < 8; ++nt)
#pragma unroll
            for (int r = 0; r < 4; ++r) acc[mt][nt][r] = 0.f;

    const int sub = lane >> 3, l7 = lane & 7;

    for (int i = 0; i < NCW; ++i) {
        CP_ASYNC_WAIT1();
        __syncthreads();
        if (i + 2 < NCW) load_stage((i + 2) % 3, i + 2);
        CP_ASYNC_COMMIT();

        const uint32_t sA = sb + (i % 3) * STGW;
        const uint32_t sB = sA + 16384;

#pragma unroll
        for (int ks = 0; ks < 4; ++ks) {
            uint32_t ah[2][4];
#pragma unroll
            for (int mt = 0; mt < 2; ++mt) {
                int row = wm * 32 + mt * 16 + ((sub & 1) << 3) + l7;
                int ch = 2 * ks + (sub >> 1);
                uint32_t off = SWOFF(row, ch);
                LDSM4(ah[mt][0], ah[mt][1], ah[mt][2], ah[mt][3], sA + off);
            }
#pragma unroll
            for (int ntp = 0; ntp < 4; ++ntp) {
                int row = wn * 64 + ntp * 16 + ((sub >> 1) << 3) + l7;
                int ch = 2 * ks + (sub & 1);
                uint32_t off = SWOFF(row, ch);
                uint32_t bh2[2][2];
                LDSM4(bh2[0][0], bh2[0][1], bh2[1][0], bh2[1][1], sB + off);
#pragma unroll
                for (int h = 0; h < 2; ++h) {
                    const int nt = 2 * ntp + h;
#pragma unroll
                    for (int mt = 0; mt < 2; ++mt)
                        MMA_F16(acc[mt][nt], ah[mt], bh2[h]);
                }
            }
        }
    }

#pragma unroll
    for (int mt = 0; mt < 2; ++mt)
#pragma unroll
        for (int nt = 0; nt < 8; ++nt) {
            int row = r0 + wm * 32 + mt * 16 + (lane >> 2);
            int col = c0 + wn * 64 + nt * 8 + 2 * (lane & 3);
            *(float2*)(F0 + (size_t)row * DM + col) =
                make_float2(acc[mt][nt][0], acc[mt][nt][1]);
            *(float2*)(F0 + (size_t)(row + 8) * DM + col) =
                make_float2(acc[mt][nt][2], acc[mt][nt][3]);
        }
}

// ===========================================================================
// MMA flash attention: 64-query tile, 128 threads, 4 CTAs/SM target.
// log2-domain softmax: scores scaled by SC_L2 via FMA, ex2.approx.
// ===========================================================================
#define ATT_STG 24832
#define ATT_SMEM (2 * ATT_STG)

__global__ __launch_bounds__(128, 4) void attn_mma(
    const __half* __restrict__ qbh, const __half* __restrict__ qbl,
    const __half* __restrict__ cbh, const __half* __restrict__ cbl,
    const __half* __restrict__ vbh,
    const float* __restrict__ tsg,
    __half* __restrict__ avh)
{
    extern __shared__ char sm[];
    const uint32_t sb = smem_to_u32(sm);

    const int tid = threadIdx.x;
    const int wid = tid >> 5, lane = tid & 31;
    const int sub = lane >> 3, l7 = lane & 7;
    const int i0 = blockIdx.x * 64, n = blockIdx.y, b = blockIdx.z;

    const size_t kvb = ((size_t)(b * NHEAD + n) * QL) * DH * 2;
    const char* chg = (const char*)cbh + kvb;
    const char* clg = (const char*)cbl + kvb;
    const char* vhg = (const char*)vbh + kvb;
    const char* tg = (const char*)(tsg + (size_t)(b * NHEAD + n) * QL);

    {
        const char* qhg = (const char*)qbh + ((size_t)(b * QL + i0) * DM + n * DH) * 2;
        const char* qlg = (const char*)qbl + ((size_t)(b * QL + i0) * DM + n * DH) * 2;
#pragma unroll
        for (int r = 0; r < 4; ++r) {
            int id = r * 128 + tid;
            int row = id >> 3, ch = id & 7;
            uint32_t o = SWOFF(row, ch);
            CP_ASYNC16(sb + o, qhg + (size_t)row * 2048 + ch * 16);
            CP_ASYNC16(sb + 8192 + o, qlg + (size_t)row * 2048 + ch * 16);
        }
        CP_ASYNC_COMMIT();
    }

    auto load_stage = [&](int s, int jt) {
        const uint32_t st = sb + s * ATT_STG;
        const size_t go = (size_t)jt * 64 * 128;
#pragma unroll
        for (int r = 0; r < 4; ++r) {
            int id = r * 128 + tid;
            int row = id >> 3, ch = id & 7;
            uint32_t o = SWOFF(row, ch);
            size_t g = go + (size_t)row * 128 + ch * 16;
            CP_ASYNC16(st + o, chg + g);
            CP_ASYNC16(st + 8192 + o, clg + g);
            CP_ASYNC16(st + 16384 + o, vhg + g);
        }
        if (tid < 16) CP_ASYNC16(st + 24576 + tid * 16, tg + (size_t)jt * 256 + tid * 16);
    };

    load_stage(1, 0); CP_ASYNC_COMMIT();

    CP_ASYNC_WAIT1();
    __syncthreads();

    uint32_t qhf[4][4], qlf[4][4];
#pragma unroll
    for (int kc = 0; kc < 4; ++kc) {
        int row = wid * 16 + ((sub & 1) << 3) + l7;
        int ch = 2 * kc + (sub >> 1);
        uint32_t o = SWOFF(row, ch);
        LDSM4(qhf[kc][0], qhf[kc][1], qhf[kc][2], qhf[kc][3], sb + o);
        LDSM4(qlf[kc][0], qlf[kc][1], qlf[kc][2], qlf[kc][3], sb + 8192 + o);
    }
    __syncthreads();

    load_stage(0, 1); CP_ASYNC_COMMIT();

    float o_[8][4];
    float m0 = -1e30f, m1 = -1e30f, l0 = 0.f, l1 = 0.f;
#pragma unroll
    for (int t = 0; t < 8; ++t)
#pragma unroll
        for (int r = 0; r < 4; ++r) o_[t][r] = 0.f;

    for (int jt = 0; jt < 16; ++jt) {
        CP_ASYNC_WAIT1();
        __syncthreads();

        const int s = (jt + 1) & 1;
        const uint32_t st = sb + s * ATT_STG;
        const float* tsp = (const float*)(sm + s * ATT_STG + 24576);

        float sc[8][4];
#pragma unroll
        for (int t = 0; t < 8; ++t)
#pragma unroll
            for (int r = 0; r < 4; ++r) sc[t][r] = 0.f;

#pragma unroll
        for (int kc = 0; kc < 4; ++kc) {
#pragma unroll
            for (int p = 0; p < 4; ++p) {
                int row = p * 16 + ((sub >> 1) << 3) + l7;
                int ch = 2 * kc + (sub & 1);
                uint32_t o = SWOFF(row, ch);
                uint32_t bh[2][2], bl[2][2];
                LDSM4(bh[0][0], bh[0][1], bh[1][0], bh[1][1], st + o);
                LDSM4(bl[0][0], bl[0][1], bl[1][0], bl[1][1], st + 8192 + o);
#pragma unroll
                for (int h = 0; h < 2; ++h) {
                    MMA_F16(sc[2 * p + h], qhf[kc], bh[h]);
                    MMA_F16(sc[2 * p + h], qhf[kc], bl[h]);
                    MMA_F16(sc[2 * p + h], qlf[kc], bh[h]);
                }
            }
        }

        // fold score scale + (pre-scaled) ts via single FMA: log2-domain logits
#pragma unroll
        for (int t = 0; t < 8; ++t) {
            float2 tv = *(const float2*)(tsp + t * 8 + (lane & 3) * 2);
            sc[t][0] = sc[t][0] * SC_L2 + tv.x;
            sc[t][1] = sc[t][1] * SC_L2 + tv.y;
            sc[t][2] = sc[t][2] * SC_L2 + tv.x;
            sc[t][3] = sc[t][3] * SC_L2 + tv.y;
        }

        float mx0 = -1e30f, mx1 = -1e30f;
#pragma unroll
        for (int t = 0; t < 8; ++t) {
            mx0 = fmaxf(mx0, fmaxf(sc[t][0], sc[t][1]));
            mx1 = fmaxf(mx1, fmaxf(sc[t][2], sc[t][3]));
        }
        mx0 = fmaxf(mx0, __shfl_xor_sync(0xffffffffu, mx0, 1));
        mx0 = fmaxf(mx0, __shfl_xor_sync(0xffffffffu, mx0, 2));
        mx1 = fmaxf(mx1, __shfl_xor_sync(0xffffffffu, mx1, 1));
        mx1 = fmaxf(mx1, __shfl_xor_sync(0xffffffffu, mx1, 2));
        const float nm0 = fmaxf(m0, mx0), nm1 = fmaxf(m1, mx1);
        const float a0 = ex2f(m0 - nm0), a1 = ex2f(m1 - nm1);
        m0 = nm0; m1 = nm1;

        float sum0 = 0.f, sum1 = 0.f;
#pragma unroll
        for (int t = 0; t < 8; ++t) {
            sc[t][0] = ex2f(sc[t][0] - nm0);
            sc[t][1] = ex2f(sc[t][1] - nm0);
            sc[t][2] = ex2f(sc[t][2] - nm1);
            sc[t][3] = ex2f(sc[t][3] - nm1);
            sum0 += sc[t][0] + sc[t][1];
            sum1 += sc[t][2] + sc[t][3];
        }
        sum0 += __shfl_xor_sync(0xffffffffu, sum0, 1);
        sum0 += __shfl_xor_sync(0xffffffffu, sum0, 2);
        sum1 += __shfl_xor_sync(0xffffffffu, sum1, 1);
        sum1 += __shfl_xor_sync(0xffffffffu, sum1, 2);
        l0 = l0 * a0 + sum0;
        l1 = l1 * a1 + sum1;
#pragma unroll
        for (int t = 0; t < 8; ++t) {
            o_[t][0] *= a0; o_[t][1] *= a0;
            o_[t][2] *= a1; o_[t][3] *= a1;
        }

#pragma unroll
        for (int kc = 0; kc < 4; ++kc) {
            uint32_t ah[4];
#pragma unroll
            for (int h = 0; h < 2; ++h) {
                const int t = 2 * kc + h;
                __half2 p01 = __floats2half2_rn(sc[t][0], sc[t][1]);
                __half2 p23 = __floats2half2_rn(sc[t][2], sc[t][3]);
                ah[2 * h + 0] = *(uint32_t*)&p01;
                ah[2 * h + 1] = *(uint32_t*)&p23;
            }
#pragma unroll
            for (int g = 0; g < 4; ++g) {
                int row = 16 * kc + ((sub & 1) << 3) + l7;
                int ch = 2 * g + (sub >> 1);
                uint32_t o = SWOFF(row, ch);
                uint32_t vh[2][2];
                LDSM4T(vh[0][0], vh[0][1], vh[1][0], vh[1][1], st + 16384 + o);
#pragma unroll
                for (int h = 0; h < 2; ++h)
                    MMA_F16(o_[2 * g + h], ah, vh[h]);
            }
        }

        __syncthreads();
        if (jt + 2 < 16) load_stage(s, jt + 2);
        CP_ASYNC_COMMIT();
    }

    const float inv0 = 1.f / l0, inv1 = 1.f / l1;
    const int row0 = i0 + wid * 16 + (lane >> 2);
#pragma unroll
    for (int t = 0; t < 8; ++t) {
        const int col = n * DH + t * 8 + (lane & 3) * 2;
        float v0 = o_[t][0] * inv0, v1 = o_[t][1] * inv0;
        float v2 = o_[t][2] * inv1, v3 = o_[t][3] * inv1;
        size_t p0 = (size_t)(b * QL + row0) * DM + col;
        size_t p1 = (size_t)(b * QL + row0 + 8) * DM + col;
        *(__half2*)(avh + p0) = __floats2half2_rn(v0, v1);
        *(__half2*)(avh + p1) = __floats2half2_rn(v2, v3);
    }
}

// ===========================================================================
// Residual + LayerNorm
// ===========================================================================
__global__ __launch_bounds__(256) void ln_kernel(
    const float* __restrict__ w, const float* __restrict__ ao,
    const float* __restrict__ gamma, const float* __restrict__ beta,
    float* __restrict__ out)
{
    __shared__ float ssum[8], ssq[8];
    const int row = blockIdx.x;
    const int tid = threadIdx.x;
    const size_t base = (size_t)row * DM + tid * 4;

    float4 x = *(const float4*)(w + base);
    float4 a = *(const float4*)(ao + base);
    x.x += a.x; x.y += a.y; x.z += a.z; x.w += a.w;

    float sum = x.x + x.y + x.z + x.w;
    float sq = x.x * x.x + x.y * x.y + x.z * x.z + x.w * x.w;
#pragma unroll
    for (int off = 16; off; off >>= 1) {
        sum += __shfl_xor_sync(0xffffffffu, sum, off);
        sq += __shfl_xor_sync(0xffffffffu, sq, off);
    }
    const int wid = tid >> 5;
    if ((tid & 31) == 0) { ssum[wid] = sum; ssq[wid] = sq; }
    __syncthreads();
    sum = 0.f; sq = 0.f;
#pragma unroll
    for (int i = 0; i < 8; ++i) { sum += ssum[i]; sq += ssq[i]; }

    const float mu = sum * (1.f / DM);
    const float var = sq * (1.f / DM) - mu * mu;
    const float inv = rsqrtf(var + 1e-5f);

    float4 g = *(const float4*)(gamma + (size_t)tid * 4);
    float4 be = *(const float4*)(beta + (size_t)tid * 4);
    float4 r;
    r.x = (x.x - mu) * inv * g.x + be.x;
    r.y = (x.y - mu) * inv * g.y + be.y;
    r.z = (x.z - mu) * inv * g.z + be.z;
    r.w = (x.w - mu) * inv * g.w + be.w;
    *(float4*)(out + base) = r;
}

// ===========================================================================
extern "C" void kernel_launch(void* const* d_in, const int* in_sizes, int n_in,
                              void* d_out, int out_size)
{
    (void)in_sizes; (void)n_in; (void)out_size;
    const float* w      = (const float*)d_in[0];
    const float* r_emb  = (const float*)d_in[1];
    const float* r_w_b  = (const float*)d_in[2];
    const float* r_bias = (const float*)d_in[3];
    const float* Wq     = (const float*)d_in[4];
    const float* Wk     = (const float*)d_in[5];
    const float* Wv     = (const float*)d_in[6];
    const float* Wo     = (const float*)d_in[7];
    const float* gamma  = (const float*)d_in[8];
    const float* beta   = (const float*)d_in[9];
    float* out = (float*)d_out;

    float *ao, *tsg;
    __half *wh, *wl, *avh, *bh, *bl;
    __half *qbh, *qbl, *cbh, *cbl, *vbh;
    cudaGetSymbolAddress((void**)&ao, g_ao);
    cudaGetSymbolAddress((void**)&wh, g_wh);
    cudaGetSymbolAddress((void**)&wl, g_wl);
    cudaGetSymbolAddress((void**)&avh, g_avh);
    cudaGetSymbolAddress((void**)&bh, g_bh);
    cudaGetSymbolAddress((void**)&bl, g_bl);
    cudaGetSymbolAddress((void**)&qbh, g_qbh);
    cudaGetSymbolAddress((void**)&qbl, g_qbl);
    cudaGetSymbolAddress((void**)&cbh, g_cbh);
    cudaGetSymbolAddress((void**)&cbl, g_cbl);
    cudaGetSymbolAddress((void**)&vbh, g_vbh);
    cudaGetSymbolAddress((void**)&tsg, g_ts);

    prep_all<<<dim3(32, 32, 8), 256>>>(w, Wq, Wk, Wv, Wo, wh, wl, bh, bl);

    cudaFuncSetAttribute(gemm_qkv,
                         cudaFuncAttributeMaxDynamicSharedMemorySize, SMEM_G64);
    gemm_qkv<<<dim3(8, 192), 128, SMEM_G64>>>(
        wh, wl, bh, bl, r_emb, r_w_b, r_bias,
        qbh, qbl, cbh, cbl, vbh, tsg);

    cudaFuncSetAttribute(attn_mma,
                         cudaFuncAttributeMaxDynamicSharedMemorySize, ATT_SMEM);
    attn_mma<<<dim3(QL / 64, NHEAD, BB), 128, ATT_SMEM>>>(
        qbh, qbl, cbh, cbl, vbh, tsg, avh);

    cudaFuncSetAttribute(gemm_wo,
                         cudaFuncAttributeMaxDynamicSharedMemorySize, SMEM_WO);
    gemm_wo<<<dim3(8, 32), 256, SMEM_WO>>>(
        avh, bh + 3 * (size_t)DM * DM, ao);

    ln_kernel<<<MTOT, 256>>>(w, ao, gamma, beta, out);
}

// round 17
// speedup vs baseline: 1.0835x; 1.0023x over previous
#include <cuda_runtime.h>
#include <cuda_fp16.h>
#include <cstdint>

#define BB 4
#define QL 1024
#define DM 1024
#define NHEAD 16
#define DH 64
#define MTOT (BB * QL)  // 4096

// scale folded into log2 domain: 0.125 * log2(e)
#define SC_L2 0.18033688f

// fp16 scratch
__device__ __half g_ao[(size_t)MTOT * DM];
__device__ __half g_wh[(size_t)MTOT * DM];
__device__ __half g_wl[(size_t)MTOT * DM];
__device__ __half g_avh[(size_t)MTOT * DM];
__device__ __half g_bh[(size_t)4 * DM * DM];
__device__ __half g_bl[(size_t)4 * DM * DM];
// attention operands
__device__ __half g_qbh[(size_t)MTOT * DM];
__device__ __half g_qbl[(size_t)MTOT * DM];
__device__ __half g_cbh[(size_t)BB * NHEAD * QL * DH];
__device__ __half g_cbl[(size_t)BB * NHEAD * QL * DH];
__device__ __half g_vbh[(size_t)BB * NHEAD * QL * DH];
__device__ float g_ts[(size_t)BB * NHEAD * QL];

// ===========================================================================
// PTX helpers (portable sm_80/90-class only)
// ===========================================================================
__device__ __forceinline__ uint32_t smem_to_u32(const void* p) {
    uint32_t a;
    asm("{ .reg .u64 t; cvta.to.shared.u64 t, %1; cvt.u32.u64 %0, t; }"
        : "=r"(a) : "l"(p));
    return a;
}
__device__ __forceinline__ float ex2f(float x) {
    float r;
    asm("ex2.approx.f32 %0, %1;" : "=f"(r) : "f"(x));
    return r;
}
#define CP_ASYNC16(s, g) \
    asm volatile("cp.async.cg.shared.global [%0], [%1], 16;" :: "r"(s), "l"(g) : "memory")
#define CP_ASYNC_COMMIT() asm volatile("cp.async.commit_group;" ::: "memory")
#define CP_ASYNC_WAIT1() asm volatile("cp.async.wait_group 1;" ::: "memory")

#define LDSM4(r0, r1, r2, r3, addr)                                            \
    asm volatile("ldmatrix.sync.aligned.m8n8.x4.shared.b16 {%0,%1,%2,%3}, [%4];" \
                 : "=r"(r0), "=r"(r1), "=r"(r2), "=r"(r3) : "r"(addr))
#define LDSM4T(r0, r1, r2, r3, addr)                                           \
    asm volatile("ldmatrix.sync.aligned.m8n8.x4.trans.shared.b16 {%0,%1,%2,%3}, [%4];" \
                 : "=r"(r0), "=r"(r1), "=r"(r2), "=r"(r3) : "r"(addr))

#define MMA_F16(d, a, b)                                                       \
    asm volatile("mma.sync.aligned.m16n8k16.row.col.f32.f16.f16.f32 "          \
                 "{%0,%1,%2,%3}, {%4,%5,%6,%7}, {%8,%9}, {%0,%1,%2,%3};"       \
                 : "+f"((d)[0]), "+f"((d)[1]), "+f"((d)[2]), "+f"((d)[3])      \
                 : "r"((a)[0]), "r"((a)[1]), "r"((a)[2]), "r"((a)[3]),         \
                   "r"((b)[0]), "r"((b)[1]))

// 64B rows (32 fp16), 4x16B chunks
#define SW64(row, ch) ((row) * 64 + (((ch) ^ (((row) >> 1) & 3)) << 4))
// 128B rows (64 fp16), 8x16B chunks
#define SWOFF(row, ch) ((row) * 128 + (((ch) ^ ((row) & 7)) << 4))

// ===========================================================================
// prep_all: z<4 -> weight transpose+split; z>=4 -> activation split (fp16)
// ===========================================================================
__global__ __launch_bounds__(256) void prep_all(
    const float* __restrict__ w,
    const float* __restrict__ s0, const float* __restrict__ s1,
    const float* __restrict__ s2, const float* __restrict__ s3,
    __half* __restrict__ wh, __half* __restrict__ wl,
    __half* __restrict__ bh, __half* __restrict__ bl)
{
    const int z = blockIdx.z;
    if (z >= 4) {
        int i = (((z - 4) * 32 + blockIdx.y) * 32 + blockIdx.x) * 256 + threadIdx.x;
        float4 a = ((const float4*)w)[i];
        __half h0 = __float2half_rn(a.x), h1 = __float2half_rn(a.y);
        __half h2 = __float2half_rn(a.z), h3 = __float2half_rn(a.w);
        ((__half2*)wh)[i * 2 + 0] = __halves2half2(h0, h1);
        ((__half2*)wh)[i * 2 + 1] = __halves2half2(h2, h3);
        ((__half2*)wl)[i * 2 + 0] = __halves2half2(
            __float2half_rn(a.x - __half2float(h0)),
            __float2half_rn(a.y - __half2float(h1)));
        ((__half2*)wl)[i * 2 + 1] = __halves2half2(
            __float2half_rn(a.z - __half2float(h2)),
            __float2half_rn(a.w - __half2float(h3)));
        return;
    }
    __shared__ float t[32][33];
    const float* S = z == 0 ? s0 : z == 1 ? s1 : z == 2 ? s2 : s3;
    __half* H = bh + (size_t)z * DM * DM;
    __half* L = bl + (size_t)z * DM * DM;
    const int x = blockIdx.x * 32, y = blockIdx.y * 32;
    const int tx = threadIdx.x & 31, ty = threadIdx.x >> 5;
#pragma unroll
    for (int i = 0; i < 32; i += 8)
        t[ty + i][tx] = S[(size_t)(y + ty + i) * DM + x + tx];
    __syncthreads();
    const int c = (threadIdx.x & 15) * 2;
    const int rb = threadIdx.x >> 4;
#pragma unroll
    for (int i = 0; i < 32; i += 16) {
        const int r = rb + i;
        float a0 = t[c][r], a1 = t[c + 1][r];
        __half h0 = __float2half_rn(a0), h1 = __float2half_rn(a1);
        size_t idx = (size_t)(x + r) * DM + y + c;
        *(__half2*)(H + idx) = __halves2half2(h0, h1);
        *(__half2*)(L + idx) = __halves2half2(
            __float2half_rn(a0 - __half2float(h0)),
            __float2half_rn(a1 - __half2float(h1)));
    }
}

// ===========================================================================
// QKV GEMM: CTA 64x128, 128 threads, 3 CTAs/SM, grid (8,192) mat-major.
// mat 0 (Q), 1 (K->C + ts*SC_L2): fp16x3. mat 2 (V): fp16 single pass.
// ===========================================================================
#define GK 1024
#define NCH 32
#define STG3 24576
#define SMEM_G64 (3 * STG3)

__global__ __launch_bounds__(128, 3) void gemm_qkv(
    const __half* __restrict__ Ah, const __half* __restrict__ Al,
    const __half* __restrict__ Bh, const __half* __restrict__ Bl,
    const float* __restrict__ remb, const float* __restrict__ rwb,
    const float* __restrict__ rbias,
    __half* __restrict__ Qh, __half* __restrict__ Ql,
    __half* __restrict__ Cbh, __half* __restrict__ Cbl,
    __half* __restrict__ Vbh,
    float* __restrict__ tsg)
{
    extern __shared__ char smem[];
    const uint32_t sb = smem_to_u32(smem);
    const int tid = threadIdx.x;
    const int wid = tid >> 5, lane = tid & 31;
    const int wm = wid >> 1, wn = wid & 1;
    const int mat = blockIdx.y >> 6;
    const int c0 = blockIdx.x * 128;
    const int r0 = (blockIdx.y & 63) * 64;
    const bool third = (mat != 2);

    const char* AgH = (const char*)(Ah + (size_t)r0 * GK);
    const char* AgL = (const char*)(Al + (size_t)r0 * GK);
    const char* BgH = (const char*)(Bh + (size_t)mat * DM * DM + (size_t)c0 * GK);
    const char* BgL = (const char*)(Bl + (size_t)mat * DM * DM + (size_t)c0 * GK);

    auto load_stage = [&](int st, int ck) {
        const uint32_t s0 = sb + st * STG3;
        const size_t gofs = (size_t)ck * 64;
#pragma unroll
        for (int h = 0; h < 2; ++h) {
            int idx = h * 128 + tid;
            int row = idx >> 2, ch = idx & 3;
            uint32_t o = SW64(row, ch);
            size_t g = (size_t)row * 2048 + gofs + ch * 16;
            CP_ASYNC16(s0 + o, AgH + g);
            if (third) CP_ASYNC16(s0 + 4096 + o, AgL + g);
        }
#pragma unroll
        for (int h = 0; h < 4; ++h) {
            int idx = h * 128 + tid;
            int row = idx >> 2, ch = idx & 3;
            uint32_t o = SW64(row, ch);
            size_t g = (size_t)row * 2048 + gofs + ch * 16;
            CP_ASYNC16(s0 + 8192 + o, BgH + g);
            if (third) CP_ASYNC16(s0 + 16384 + o, BgL + g);
        }
    };

    load_stage(0, 0); CP_ASYNC_COMMIT();
    load_stage(1, 1); CP_ASYNC_COMMIT();

    float acc[2][8][4];
#pragma unroll
    for (int mt = 0; mt < 2; ++mt)
#pragma unroll
        for (int nt = 0; nt < 8; ++nt)
#pragma unroll
            for (int r = 0; r < 4; ++r) acc[mt][nt][r] = 0.f;

    const int sub = lane >> 3, l7 = lane & 7;

    for (int i = 0; i < NCH; ++i) {
        CP_ASYNC_WAIT1();
        __syncthreads();
        if (i + 2 < NCH) load_stage((i + 2) % 3, i + 2);
        CP_ASYNC_COMMIT();

        const uint32_t sA = sb + (i % 3) * STG3;
        const uint32_t sB = sA + 8192;

#pragma unroll
        for (int ks = 0; ks < 2; ++ks) {
            uint32_t ah[2][4], al[2][4], bh2[4][2][2], bl2[4][2][2];
#pragma unroll
            for (int mt = 0; mt < 2; ++mt) {
                int row = wm * 32 + mt * 16 + ((sub & 1) << 3) + l7;
                int ch = 2 * ks + (sub >> 1);
                uint32_t off = SW64(row, ch);
                LDSM4(ah[mt][0], ah[mt][1], ah[mt][2], ah[mt][3], sA + off);
                if (third)
                    LDSM4(al[mt][0], al[mt][1], al[mt][2], al[mt][3],
                          sA + 4096 + off);
            }
#pragma unroll
            for (int ntp = 0; ntp < 4; ++ntp) {
                int row = wn * 64 + ntp * 16 + ((sub >> 1) << 3) + l7;
                int ch = 2 * ks + (sub & 1);
                uint32_t off = SW64(row, ch);
                LDSM4(bh2[ntp][0][0], bh2[ntp][0][1], bh2[ntp][1][0],
                      bh2[ntp][1][1], sB + off);
                if (third)
                    LDSM4(bl2[ntp][0][0], bl2[ntp][0][1], bl2[ntp][1][0],
                          bl2[ntp][1][1], sB + 8192 + off);
            }
#pragma unroll
            for (int ntp = 0; ntp < 4; ++ntp)
#pragma unroll
                for (int h = 0; h < 2; ++h)
#pragma unroll
                    for (int mt = 0; mt < 2; ++mt)
                        MMA_F16(acc[mt][2 * ntp + h], ah[mt], bh2[ntp][h]);
            if (third) {
#pragma unroll
                for (int ntp = 0; ntp < 4; ++ntp)
#pragma unroll
                    for (int h = 0; h < 2; ++h)
#pragma unroll
                        for (int mt = 0; mt < 2; ++mt) {
                            MMA_F16(acc[mt][2 * ntp + h], ah[mt], bl2[ntp][h]);
                            MMA_F16(acc[mt][2 * ntp + h], al[mt], bh2[ntp][h]);
                        }
            }
        }
    }

    if (mat == 0) {
#pragma unroll
        for (int mt = 0; mt < 2; ++mt)
#pragma unroll
            for (int nt = 0; nt < 8; ++nt) {
                int row = r0 + wm * 32 + mt * 16 + (lane >> 2);
                int col = c0 + wn * 64 + nt * 8 + 2 * (lane & 3);
                size_t p0 = (size_t)row * DM + col;
                size_t p1 = (size_t)(row + 8) * DM + col;
                float v0 = acc[mt][nt][0], v1 = acc[mt][nt][1];
                float v2 = acc[mt][nt][2], v3 = acc[mt][nt][3];
                __half2 h01 = __floats2half2_rn(v0, v1);
                __half2 h23 = __floats2half2_rn(v2, v3);
                *(__half2*)(Qh + p0) = h01;
                *(__half2*)(Qh + p1) = h23;
                *(__half2*)(Ql + p0) = __floats2half2_rn(
                    v0 - __half2float(h01.x), v1 - __half2float(h01.y));
                *(__half2*)(Ql + p1) = __floats2half2_rn(
                    v2 - __half2float(h23.x), v3 - __half2float(h23.y));
            }
    } else {
        const int n = (blockIdx.x << 1) + wn;
        float rwv[8][2];
        if (mat == 1) {
#pragma unroll
            for (int nt = 0; nt < 8; ++nt) {
                float2 t = *(const float2*)(rwb + n * DH + nt * 8 + 2 * (lane & 3));
                rwv[nt][0] = t.x; rwv[nt][1] = t.y;
            }
        }
#pragma unroll
        for (int mt = 0; mt < 2; ++mt) {
#pragma unroll
            for (int half = 0; half < 2; ++half) {
                const int row = r0 + wm * 32 + mt * 16 + (lane >> 2) + half * 8;
                const int b = row >> 10, j = row & 1023;
                const bool has = (j + 1) < QL;
                float dot = 0.f;
                float vals[8][2];
#pragma unroll
                for (int nt = 0; nt < 8; ++nt) {
                    float v0 = acc[mt][nt][half * 2 + 0];
                    float v1 = acc[mt][nt][half * 2 + 1];
                    if (mat == 1) {
                        dot += rwv[nt][0] * v0 + rwv[nt][1] * v1;
                        const int d = nt * 8 + 2 * (lane & 3);
                        float2 re = has
                            ? *(const float2*)(remb + ((size_t)(j + 1) * NHEAD + n) * DH + d)
                            : make_float2(0.f, 0.f);
                        v0 += re.x; v1 += re.y;
                    }
                    vals[nt][0] = v0; vals[nt][1] = v1;
                }
                const size_t base =
                    ((size_t)(b * NHEAD + n) * QL + j) * DH + 2 * (lane & 3);
                if (mat == 1) {
#pragma unroll
                    for (int nt = 0; nt < 8; ++nt) {
                        __half2 h2 = __floats2half2_rn(vals[nt][0], vals[nt][1]);
                        *(__half2*)(Cbh + base + nt * 8) = h2;
                        *(__half2*)(Cbl + base + nt * 8) = __floats2half2_rn(
                            vals[nt][0] - __half2float(h2.x),
                            vals[nt][1] - __half2float(h2.y));
                    }
                    dot += __shfl_xor_sync(0xffffffffu, dot, 1);
                    dot += __shfl_xor_sync(0xffffffffu, dot, 2);
                    if ((lane & 3) == 0)
                        tsg[(size_t)(b * NHEAD + n) * QL + j] =
                            (dot + (has ? rbias[(size_t)(j + 1) * NHEAD + n] : 0.f))
                            * SC_L2;
                } else {
#pragma unroll
                    for (int nt = 0; nt < 8; ++nt)
                        *(__half2*)(Vbh + base + nt * 8) =
                            __floats2half2_rn(vals[nt][0], vals[nt][1]);
                }
            }
        }
    }
}

// ===========================================================================
// Wo GEMM: CTA 128x128, 256 threads, 2 CTAs/SM, single fp16 pass, BK=64.
// Output ao stored as fp16.
// ===========================================================================
#define NCW 16
#define STGW 32768
#define SMEM_WO (3 * STGW)

__global__ __launch_bounds__(256, 2) void gemm_wo(
    const __half* __restrict__ Ah, const __half* __restrict__ Bh,
    __half* __restrict__ F0)
{
    extern __shared__ char smem[];
    const uint32_t sb = smem_to_u32(smem);
    const int tid = threadIdx.x;
    const int wid = tid >> 5, lane = tid & 31;
    const int wm = wid >> 1, wn = wid & 1;
    const int c0 = blockIdx.x * 128;
    const int r0 = blockIdx.y * 128;

    const char* AgH = (const char*)(Ah + (size_t)r0 * GK);
    const char* BgH = (const char*)(Bh + (size_t)c0 * GK);

    auto load_stage = [&](int st, int ck) {
        const uint32_t s0 = sb + st * STGW;
        const size_t gofs = (size_t)ck * 128;
#pragma unroll
        for (int h = 0; h < 4; ++h) {
            int idx = h * 256 + tid;
            int row = idx >> 3, ch = idx & 7;
            uint32_t o = SWOFF(row, ch);
            size_t g = (size_t)row * 2048 + gofs + ch * 16;
            CP_ASYNC16(s0 + o, AgH + g);
            CP_ASYNC16(s0 + 16384 + o, BgH + g);
        }
    };

    load_stage(0, 0); CP_ASYNC_COMMIT();
    load_stage(1, 1); CP_ASYNC_COMMIT();

    float acc[2][8][4];
#pragma unroll
    for (int mt = 0; mt < 2; ++mt)
#pragma unroll
        for (int nt = 0; nt < 8; ++nt)
#pragma unroll
            for (int r = 0; r < 4; ++r) acc[mt][nt][r] = 0.f;

    const int sub = lane >> 3, l7 = lane & 7;

    for (int i = 0; i < NCW; ++i) {
        CP_ASYNC_WAIT1();
        __syncthreads();
        if (i + 2 < NCW) load_stage((i + 2) % 3, i + 2);
        CP_ASYNC_COMMIT();

        const uint32_t sA = sb + (i % 3) * STGW;
        const uint32_t sB = sA + 16384;

#pragma unroll
        for (int ks = 0; ks < 4; ++ks) {
            uint32_t ah[2][4];
#pragma unroll
            for (int mt = 0; mt < 2; ++mt) {
                int row = wm * 32 + mt * 16 + ((sub & 1) << 3) + l7;
                int ch = 2 * ks + (sub >> 1);
                uint32_t off = SWOFF(row, ch);
                LDSM4(ah[mt][0], ah[mt][1], ah[mt][2], ah[mt][3], sA + off);
            }
#pragma unroll
            for (int ntp = 0; ntp < 4; ++ntp) {
                int row = wn * 64 + ntp * 16 + ((sub >> 1) << 3) + l7;
                int ch = 2 * ks + (sub & 1);
                uint32_t off = SWOFF(row, ch);
                uint32_t bh2[2][2];
                LDSM4(bh2[0][0], bh2[0][1], bh2[1][0], bh2[1][1], sB + off);
#pragma unroll
                for (int h = 0; h < 2; ++h) {
                    const int nt = 2 * ntp + h;
#pragma unroll
                    for (int mt = 0; mt < 2; ++mt)
                        MMA_F16(acc[mt][nt], ah[mt], bh2[h]);
                }
            }
        }
    }

#pragma unroll
    for (int mt = 0; mt < 2; ++mt)
#pragma unroll
        for (int nt = 0; nt < 8; ++nt) {
            int row = r0 + wm * 32 + mt * 16 + (lane >> 2);
            int col = c0 + wn * 64 + nt * 8 + 2 * (lane & 3);
            *(__half2*)(F0 + (size_t)row * DM + col) =
                __floats2half2_rn(acc[mt][nt][0], acc[mt][nt][1]);
            *(__half2*)(F0 + (size_t)(row + 8) * DM + col) =
                __floats2half2_rn(acc[mt][nt][2], acc[mt][nt][3]);
        }
}

// ===========================================================================
// MMA flash attention (R16 exact): log2-domain softmax, 4 CTAs/SM target.
// ===========================================================================
#define ATT_STG 24832
#define ATT_SMEM (2 * ATT_STG)

__global__ __launch_bounds__(128, 4) void attn_mma(
    const __half* __restrict__ qbh, const __half* __restrict__ qbl,
    const __half* __restrict__ cbh, const __half* __restrict__ cbl,
    const __half* __restrict__ vbh,
    const float* __restrict__ tsg,
    __half* __restrict__ avh)
{
    extern __shared__ char sm[];
    const uint32_t sb = smem_to_u32(sm);

    const int tid = threadIdx.x;
    const int wid = tid >> 5, lane = tid & 31;
    const int sub = lane >> 3, l7 = lane & 7;
    const int i0 = blockIdx.x * 64, n = blockIdx.y, b = blockIdx.z;

    const size_t kvb = ((size_t)(b * NHEAD + n) * QL) * DH * 2;
    const char* chg = (const char*)cbh + kvb;
    const char* clg = (const char*)cbl + kvb;
    const char* vhg = (const char*)vbh + kvb;
    const char* tg = (const char*)(tsg + (size_t)(b * NHEAD + n) * QL);

    {
        const char* qhg = (const char*)qbh + ((size_t)(b * QL + i0) * DM + n * DH) * 2;
        const char* qlg = (const char*)qbl + ((size_t)(b * QL + i0) * DM + n * DH) * 2;
#pragma unroll
        for (int r = 0; r < 4; ++r) {
            int id = r * 128 + tid;
            int row = id >> 3, ch = id & 7;
            uint32_t o = SWOFF(row, ch);
            CP_ASYNC16(sb + o, qhg + (size_t)row * 2048 + ch * 16);
            CP_ASYNC16(sb + 8192 + o, qlg + (size_t)row * 2048 + ch * 16);
        }
        CP_ASYNC_COMMIT();
    }

    auto load_stage = [&](int s, int jt) {
        const uint32_t st = sb + s * ATT_STG;
        const size_t go = (size_t)jt * 64 * 128;
#pragma unroll
        for (int r = 0; r < 4; ++r) {
            int id = r * 128 + tid;
            int row = id >> 3, ch = id & 7;
            uint32_t o = SWOFF(row, ch);
            size_t g = go + (size_t)row * 128 + ch * 16;
            CP_ASYNC16(st + o, chg + g);
            CP_ASYNC16(st + 8192 + o, clg + g);
            CP_ASYNC16(st + 16384 + o, vhg + g);
        }
        if (tid < 16) CP_ASYNC16(st + 24576 + tid * 16, tg + (size_t)jt * 256 + tid * 16);
    };

    load_stage(1, 0); CP_ASYNC_COMMIT();

    CP_ASYNC_WAIT1();
    __syncthreads();

    uint32_t qhf[4][4], qlf[4][4];
#pragma unroll
    for (int kc = 0; kc < 4; ++kc) {
        int row = wid * 16 + ((sub & 1) << 3) + l7;
        int ch = 2 * kc + (sub >> 1);
        uint32_t o = SWOFF(row, ch);
        LDSM4(qhf[kc][0], qhf[kc][1], qhf[kc][2], qhf[kc][3], sb + o);
        LDSM4(qlf[kc][0], qlf[kc][1], qlf[kc][2], qlf[kc][3], sb + 8192 + o);
    }
    __syncthreads();

    load_stage(0, 1); CP_ASYNC_COMMIT();

    float o_[8][4];
    float m0 = -1e30f, m1 = -1e30f, l0 = 0.f, l1 = 0.f;
#pragma unroll
    for (int t = 0; t < 8; ++t)
#pragma unroll
        for (int r = 0; r < 4; ++r) o_[t][r] = 0.f;

    for (int jt = 0; jt < 16; ++jt) {
        CP_ASYNC_WAIT1();
        __syncthreads();

        const int s = (jt + 1) & 1;
        const uint32_t st = sb + s * ATT_STG;
        const float* tsp = (const float*)(sm + s * ATT_STG + 24576);

        float sc[8][4];
#pragma unroll
        for (int t = 0; t < 8; ++t)
#pragma unroll
            for (int r = 0; r < 4; ++r) sc[t][r] = 0.f;

#pragma unroll
        for (int kc = 0; kc < 4; ++kc) {
#pragma unroll
            for (int p = 0; p < 4; ++p) {
                int row = p * 16 + ((sub >> 1) << 3) + l7;
                int ch = 2 * kc + (sub & 1);
                uint32_t o = SWOFF(row, ch);
                uint32_t bh[2][2], bl[2][2];
                LDSM4(bh[0][0], bh[0][1], bh[1][0], bh[1][1], st + o);
                LDSM4(bl[0][0], bl[0][1], bl[1][0], bl[1][1], st + 8192 + o);
#pragma unroll
                for (int h = 0; h < 2; ++h) {
                    MMA_F16(sc[2 * p + h], qhf[kc], bh[h]);
                    MMA_F16(sc[2 * p + h], qhf[kc], bl[h]);
                    MMA_F16(sc[2 * p + h], qlf[kc], bh[h]);
                }
            }
        }

#pragma unroll
        for (int t = 0; t < 8; ++t) {
            float2 tv = *(const float2*)(tsp + t * 8 + (lane & 3) * 2);
            sc[t][0] = sc[t][0] * SC_L2 + tv.x;
            sc[t][1] = sc[t][1] * SC_L2 + tv.y;
            sc[t][2] = sc[t][2] * SC_L2 + tv.x;
            sc[t][3] = sc[t][3] * SC_L2 + tv.y;
        }

        float mx0 = -1e30f, mx1 = -1e30f;
#pragma unroll
        for (int t = 0; t < 8; ++t) {
            mx0 = fmaxf(mx0, fmaxf(sc[t][0], sc[t][1]));
            mx1 = fmaxf(mx1, fmaxf(sc[t][2], sc[t][3]));
        }
        mx0 = fmaxf(mx0, __shfl_xor_sync(0xffffffffu, mx0, 1));
        mx0 = fmaxf(mx0, __shfl_xor_sync(0xffffffffu, mx0, 2));
        mx1 = fmaxf(mx1, __shfl_xor_sync(0xffffffffu, mx1, 1));
        mx1 = fmaxf(mx1, __shfl_xor_sync(0xffffffffu, mx1, 2));
        const float nm0 = fmaxf(m0, mx0), nm1 = fmaxf(m1, mx1);
        const float a0 = ex2f(m0 - nm0), a1 = ex2f(m1 - nm1);
        m0 = nm0; m1 = nm1;

        float sum0 = 0.f, sum1 = 0.f;
#pragma unroll
        for (int t = 0; t < 8; ++t) {
            sc[t][0] = ex2f(sc[t][0] - nm0);
            sc[t][1] = ex2f(sc[t][1] - nm0);
            sc[t][2] = ex2f(sc[t][2] - nm1);
            sc[t][3] = ex2f(sc[t][3] - nm1);
            sum0 += sc[t][0] + sc[t][1];
            sum1 += sc[t][2] + sc[t][3];
        }
        sum0 += __shfl_xor_sync(0xffffffffu, sum0, 1);
        sum0 += __shfl_xor_sync(0xffffffffu, sum0, 2);
        sum1 += __shfl_xor_sync(0xffffffffu, sum1, 1);
        sum1 += __shfl_xor_sync(0xffffffffu, sum1, 2);
        l0 = l0 * a0 + sum0;
        l1 = l1 * a1 + sum1;
#pragma unroll
        for (int t = 0; t < 8; ++t) {
            o_[t][0] *= a0; o_[t][1] *= a0;
            o_[t][2] *= a1; o_[t][3] *= a1;
        }

#pragma unroll
        for (int kc = 0; kc < 4; ++kc) {
            uint32_t ah[4];
#pragma unroll
            for (int h = 0; h < 2; ++h) {
                const int t = 2 * kc + h;
                __half2 p01 = __floats2half2_rn(sc[t][0], sc[t][1]);
                __half2 p23 = __floats2half2_rn(sc[t][2], sc[t][3]);
                ah[2 * h + 0] = *(uint32_t*)&p01;
                ah[2 * h + 1] = *(uint32_t*)&p23;
            }
#pragma unroll
            for (int g = 0; g < 4; ++g) {
                int row = 16 * kc + ((sub & 1) << 3) + l7;
                int ch = 2 * g + (sub >> 1);
                uint32_t o = SWOFF(row, ch);
                uint32_t vh[2][2];
                LDSM4T(vh[0][0], vh[0][1], vh[1][0], vh[1][1], st + 16384 + o);
#pragma unroll
                for (int h = 0; h < 2; ++h)
                    MMA_F16(o_[2 * g + h], ah, vh[h]);
            }
        }

        __syncthreads();
        if (jt + 2 < 16) load_stage(s, jt + 2);
        CP_ASYNC_COMMIT();
    }

    const float inv0 = 1.f / l0, inv1 = 1.f / l1;
    const int row0 = i0 + wid * 16 + (lane >> 2);
#pragma unroll
    for (int t = 0; t < 8; ++t) {
        const int col = n * DH + t * 8 + (lane & 3) * 2;
        float v0 = o_[t][0] * inv0, v1 = o_[t][1] * inv0;
        float v2 = o_[t][2] * inv1, v3 = o_[t][3] * inv1;
        size_t p0 = (size_t)(b * QL + row0) * DM + col;
        size_t p1 = (size_t)(b * QL + row0 + 8) * DM + col;
        *(__half2*)(avh + p0) = __floats2half2_rn(v0, v1);
        *(__half2*)(avh + p1) = __floats2half2_rn(v2, v3);
    }
}

// ===========================================================================
// Residual + LayerNorm: ao now fp16
// ===========================================================================
__global__ __launch_bounds__(256) void ln_kernel(
    const float* __restrict__ w, const __half* __restrict__ ao,
    const float* __restrict__ gamma, const float* __restrict__ beta,
    float* __restrict__ out)
{
    __shared__ float ssum[8], ssq[8];
    const int row = blockIdx.x;
    const int tid = threadIdx.x;
    const size_t base = (size_t)row * DM + tid * 4;

    float4 x = *(const float4*)(w + base);
    __half2 a01 = *(const __half2*)(ao + base);
    __half2 a23 = *(const __half2*)(ao + base + 2);
    x.x += __half2float(a01.x); x.y += __half2float(a01.y);
    x.z += __half2float(a23.x); x.w += __half2float(a23.y);

    float sum = x.x + x.y + x.z + x.w;
    float sq = x.x * x.x + x.y * x.y + x.z * x.z + x.w * x.w;
#pragma unroll
    for (int off = 16; off; off >>= 1) {
        sum += __shfl_xor_sync(0xffffffffu, sum, off);
        sq += __shfl_xor_sync(0xffffffffu, sq, off);
    }
    const int wid = tid >> 5;
    if ((tid & 31) == 0) { ssum[wid] = sum; ssq[wid] = sq; }
    __syncthreads();
    sum = 0.f; sq = 0.f;
#pragma unroll
    for (int i = 0; i < 8; ++i) { sum += ssum[i]; sq += ssq[i]; }

    const float mu = sum * (1.f / DM);
    const float var = sq * (1.f / DM) - mu * mu;
    const float inv = rsqrtf(var + 1e-5f);

    float4 g = *(const float4*)(gamma + (size_t)tid * 4);
    float4 be = *(const float4*)(beta + (size_t)tid * 4);
    float4 r;
    r.x = (x.x - mu) * inv * g.x + be.x;
    r.y = (x.y - mu) * inv * g.y + be.y;
    r.z = (x.z - mu) * inv * g.z + be.z;
    r.w = (x.w - mu) * inv * g.w + be.w;
    *(float4*)(out + base) = r;
}

// ===========================================================================
extern "C" void kernel_launch(void* const* d_in, const int* in_sizes, int n_in,
                              void* d_out, int out_size)
{
    (void)in_sizes; (void)n_in; (void)out_size;
    const float* w      = (const float*)d_in[0];
    const float* r_emb  = (const float*)d_in[1];
    const float* r_w_b  = (const float*)d_in[2];
    const float* r_bias = (const float*)d_in[3];
    const float* Wq     = (const float*)d_in[4];
    const float* Wk     = (const float*)d_in[5];
    const float* Wv     = (const float*)d_in[6];
    const float* Wo     = (const float*)d_in[7];
    const float* gamma  = (const float*)d_in[8];
    const float* beta   = (const float*)d_in[9];
    float* out = (float*)d_out;

    float* tsg;
    __half *ao, *wh, *wl, *avh, *bh, *bl;
    __half *qbh, *qbl, *cbh, *cbl, *vbh;
    cudaGetSymbolAddress((void**)&ao, g_ao);
    cudaGetSymbolAddress((void**)&wh, g_wh);
    cudaGetSymbolAddress((void**)&wl, g_wl);
    cudaGetSymbolAddress((void**)&avh, g_avh);
    cudaGetSymbolAddress((void**)&bh, g_bh);
    cudaGetSymbolAddress((void**)&bl, g_bl);
    cudaGetSymbolAddress((void**)&qbh, g_qbh);
    cudaGetSymbolAddress((void**)&qbl, g_qbl);
    cudaGetSymbolAddress((void**)&cbh, g_cbh);
    cudaGetSymbolAddress((void**)&cbl, g_cbl);
    cudaGetSymbolAddress((void**)&vbh, g_vbh);
    cudaGetSymbolAddress((void**)&tsg, g_ts);

    prep_all<<<dim3(32, 32, 8), 256>>>(w, Wq, Wk, Wv, Wo, wh, wl, bh, bl);

    cudaFuncSetAttribute(gemm_qkv,
                         cudaFuncAttributeMaxDynamicSharedMemorySize, SMEM_G64);
    gemm_qkv<<<dim3(8, 192), 128, SMEM_G64>>>(
        wh, wl, bh, bl, r_emb, r_w_b, r_bias,
        qbh, qbl, cbh, cbl, vbh, tsg);

    cudaFuncSetAttribute(attn_mma,
                         cudaFuncAttributeMaxDynamicSharedMemorySize, ATT_SMEM);
    attn_mma<<<dim3(QL / 64, NHEAD, BB), 128, ATT_SMEM>>>(
        qbh, qbl, cbh, cbl, vbh, tsg, avh);

    cudaFuncSetAttribute(gemm_wo,
                         cudaFuncAttributeMaxDynamicSharedMemorySize, SMEM_WO);
    gemm_wo<<<dim3(8, 32), 256, SMEM_WO>>>(
        avh, bh + 3 * (size_t)DM * DM, ao);

    ln_kernel<<<MTOT, 256>>>(w, ao, gamma, beta, out);
}